// round 4
// baseline (speedup 1.0000x reference)
#include <cuda_runtime.h>
#include <math.h>

#define BB 2
#define LL 1024
#define XX 4
#define EE 128
#define YY 4
#define SCALE 0.08838834764831845f   // 1/sqrt(128)

// ---------------- scratch (static device globals; no allocation) ----------
__device__ float g_search[BB*XX*LL*LL];        // [b][x][l][s]   32 MB
__device__ float g_retr  [BB*XX*YY*LL*EE];     // [b][x][y][l][e] 16 MB (only y<=x used)
__device__ float g_kplus [BB*XX*YY*LL*EE];     // [b][x][y][m][f] 16 MB
__device__ float g_vpart [BB*LL*EE*XX];        // [b][l][e][x]     4 MB

__constant__ int c_xy_x[10] = {0,1,1,2,2,2,3,3,3,3};
__constant__ int c_xy_y[10] = {0,0,1,0,1,2,0,1,2,3};

// s = 3^(sigmoid(5v) + 1e-5) - 1
// Hypothesis: reference ran via jax/XLA on this GPU, so sigmoid -> __nv_expf
// based logistic and power -> __nv_powf. CUDA's expf/powf are the same
// libdevice functions -> bit-identical results.
__device__ __forceinline__ float sig_transform(float v) {
    float t = 5.0f * v;                  // f32
    float e = expf(-t);                  // __nv_expf
    float sigmoid = 1.0f / (1.0f + e);   // IEEE f32 add + div
    float sg = sigmoid + 1e-5f;          // f32 round
    float p = powf(3.0f, sg);            // __nv_powf (libdevice)
    return p - 1.0f;                     // exact (Sterbenz)
}

// ---------------- 64x64 NT GEMM core: C[m,n] = scale * sum_k A[m,k]*B[n,k] (+bias[n])
__device__ __forceinline__ void gemm_nt_tile(
    const float* __restrict__ A, int lda,
    const float* __restrict__ Bm, int ldb,
    float* __restrict__ C, int ldc,
    int K, float scale, const float* __restrict__ bias)
{
    __shared__ float As[64][17];
    __shared__ float Bs[64][17];
    const int tid = threadIdx.x;
    const int tx = tid & 15, ty = tid >> 4;
    const int row0 = blockIdx.y * 64;
    const int col0 = blockIdx.x * 64;
    float acc[4][4] = {};
    for (int kk = 0; kk < K; kk += 16) {
#pragma unroll
        for (int i = 0; i < 4; i++) {
            int idx = tid + i * 256;
            int r = idx >> 4, k = idx & 15;
            As[r][k] = A[(size_t)(row0 + r) * lda + kk + k];
            Bs[r][k] = Bm[(size_t)(col0 + r) * ldb + kk + k];
        }
        __syncthreads();
#pragma unroll
        for (int k = 0; k < 16; k++) {
            float a[4], b[4];
#pragma unroll
            for (int i = 0; i < 4; i++) a[i] = As[ty*4+i][k];
#pragma unroll
            for (int j = 0; j < 4; j++) b[j] = Bs[tx*4+j][k];
#pragma unroll
            for (int i = 0; i < 4; i++)
#pragma unroll
                for (int j = 0; j < 4; j++)
                    acc[i][j] = fmaf(a[i], b[j], acc[i][j]);
        }
        __syncthreads();
    }
#pragma unroll
    for (int i = 0; i < 4; i++) {
        int r = row0 + ty*4 + i;
#pragma unroll
        for (int j = 0; j < 4; j++) {
            int c = col0 + tx*4 + j;
            float v = acc[i][j] * scale;
            if (bias) v += bias[c];
            C[(size_t)r * ldc + c] = v;
        }
    }
}

// ---------------- 64x64 NN GEMM core: C[m,n] = sum_k A[m,k]*B[k,n]
__device__ __forceinline__ void gemm_nn_tile(
    const float* __restrict__ A, int lda,
    const float* __restrict__ Bm, int ldb,
    float* __restrict__ C, int ldc, int K)
{
    __shared__ float As[64][17];
    __shared__ float Bs[16][68];
    const int tid = threadIdx.x;
    const int tx = tid & 15, ty = tid >> 4;
    const int row0 = blockIdx.y * 64;
    const int col0 = blockIdx.x * 64;
    float acc[4][4] = {};
    for (int kk = 0; kk < K; kk += 16) {
#pragma unroll
        for (int i = 0; i < 4; i++) {
            int idx = tid + i * 256;
            int r = idx >> 4, k = idx & 15;
            As[r][k] = A[(size_t)(row0 + r) * lda + kk + k];
            int k2 = idx >> 6, n = idx & 63;
            Bs[k2][n] = Bm[(size_t)(kk + k2) * ldb + col0 + n];
        }
        __syncthreads();
#pragma unroll
        for (int k = 0; k < 16; k++) {
            float a[4], b[4];
#pragma unroll
            for (int i = 0; i < 4; i++) a[i] = As[ty*4+i][k];
#pragma unroll
            for (int j = 0; j < 4; j++) b[j] = Bs[k][tx*4+j];
#pragma unroll
            for (int i = 0; i < 4; i++)
#pragma unroll
                for (int j = 0; j < 4; j++)
                    acc[i][j] = fmaf(a[i], b[j], acc[i][j]);
        }
        __syncthreads();
    }
#pragma unroll
    for (int i = 0; i < 4; i++) {
        int r = row0 + ty*4 + i;
#pragma unroll
        for (int j = 0; j < 4; j++)
            C[(size_t)r * ldc + col0 + tx*4 + j] = acc[i][j];
    }
}

// ---------------- stage 1: scores = scale * Q K^T per (b,x) -------------
__global__ void __launch_bounds__(256) aa_k_scores(const float* __restrict__ q,
                                                   const float* __restrict__ k)
{
    int bz = blockIdx.z;               // b*X + x
    int b = bz >> 2, x = bz & 3;
    const float* A  = q + ((size_t)b*LL*XX + x) * EE;
    const float* Bm = k + ((size_t)b*LL*XX + x) * EE;
    float* C = g_search + (size_t)bz * LL * LL;
    gemm_nt_tile(A, XX*EE, Bm, XX*EE, C, LL, EE, SCALE, nullptr);
}

// ---------------- row softmax over s (in place on g_search) -------------
__global__ void __launch_bounds__(256) aa_k_softmax()
{
    size_t row = blockIdx.x;
    float* p = g_search + row * LL;
    int tid = threadIdx.x;
    float v[4];
    float m = -1e30f;
#pragma unroll
    for (int i = 0; i < 4; i++) { v[i] = p[tid + i*256]; m = fmaxf(m, v[i]); }
    __shared__ float red[256];
    red[tid] = m; __syncthreads();
    for (int s = 128; s > 0; s >>= 1) {
        if (tid < s) red[tid] = fmaxf(red[tid], red[tid+s]);
        __syncthreads();
    }
    m = red[0]; __syncthreads();
    float sum = 0.f;
#pragma unroll
    for (int i = 0; i < 4; i++) { v[i] = expf(v[i] - m); sum += v[i]; }
    red[tid] = sum; __syncthreads();
    for (int s = 128; s > 0; s >>= 1) {
        if (tid < s) red[tid] += red[tid+s];
        __syncthreads();
    }
    float inv = 1.f / red[0];
#pragma unroll
    for (int i = 0; i < 4; i++) p[tid + i*256] = v[i] * inv;
}

// ---------------- Retrieval[b,x,y] = Search[b,x] @ value[b,:,y,:] --------
__global__ void __launch_bounds__(256) aa_k_retr(const float* __restrict__ val)
{
    int t = blockIdx.z;                // 0..19 valid (b, x, y<=x)
    int b = t / 10, u = t % 10;
    int x = c_xy_x[u], y = c_xy_y[u];
    const float* A  = g_search + (size_t)(b*XX + x) * LL * LL;
    const float* Bm = val + ((size_t)b*LL*YY + y) * EE;
    float* C = g_retr + (size_t)((b*XX + x)*YY + y) * LL * EE;
    gemm_nn_tile(A, LL, Bm, YY*EE, C, EE, LL);
}

// ---------------- key_plus = Retrieval @ Wk^T + bk -----------------------
__global__ void __launch_bounds__(256) aa_k_kplus(const float* __restrict__ Wk,
                                                  const float* __restrict__ bk)
{
    int t = blockIdx.z;
    int b = t / 10, u = t % 10;
    int x = c_xy_x[u], y = c_xy_y[u];
    size_t off = (size_t)((b*XX + x)*YY + y) * LL * EE;
    gemm_nt_tile(g_retr + off, EE, Wk, EE, g_kplus + off, EE, EE, 1.0f, bk);
}

// ---------------- zero V partial ----------------------------------------
__global__ void __launch_bounds__(256) aa_k_zero_vpart()
{
    int i = blockIdx.x * 256 + threadIdx.x;
    g_vpart[i] = 0.f;
}

// ---------------- fused stage 2: scores -> softmax(Y) -> catt -> V ------
// grid: 1024 blocks = (b,x,l_tile) * 8 m-slices; each block: 64 l-rows, 2 m-tiles
#define NSLICE 8
__global__ void __launch_bounds__(256) aa_k_stage2(const float* __restrict__ qp)
{
    extern __shared__ float sm[];
    float* Qp = sm;                    // [64][132]
    float* Sm = Qp + 64*132;           // 4 * [64][65]
    float* Ch = Sm + 4*64*65;          // [16][132] (also used as [64][17])

    int bz = blockIdx.x;
    int slice = bz & (NSLICE - 1);
    int rest = bz >> 3;
    int lt = rest & 15;
    int x  = (rest >> 4) & 3;
    int b  = rest >> 6;
    const int tid = threadIdx.x;
    const int tx = tid & 15, ty = tid >> 4;
    const int l0 = lt * 64;

#pragma unroll
    for (int i = 0; i < 32; i++) {
        int idx = tid + i * 256;
        int r = idx >> 7, e = idx & 127;
        Qp[r*132 + e] = qp[(((size_t)b*LL + l0 + r)*XX + x)*EE + e];
    }
    __syncthreads();

    float vacc[4][8];
#pragma unroll
    for (int i = 0; i < 4; i++)
#pragma unroll
        for (int j = 0; j < 8; j++) vacc[i][j] = 0.f;

    const int ny = x + 1;
    const int mt0 = slice * (16 / NSLICE);
    for (int mt = mt0; mt < mt0 + 16/NSLICE; mt++) {
        const int m0 = mt * 64;
        // ---- scores for each valid y into Sm[y]
        for (int y = 0; y < ny; y++) {
            const float* Kp = g_kplus + ((size_t)((b*XX + x)*YY + y)*LL + m0) * EE;
            float sacc[4][4] = {};
            for (int kk = 0; kk < 128; kk += 16) {
#pragma unroll
                for (int i = 0; i < 4; i++) {
                    int idx = tid + i*256;
                    int r = idx >> 4, k = idx & 15;
                    Ch[r*17 + k] = Kp[(size_t)r*EE + kk + k];
                }
                __syncthreads();
#pragma unroll
                for (int k = 0; k < 16; k++) {
                    float a[4], bb[4];
#pragma unroll
                    for (int i = 0; i < 4; i++) a[i] = Qp[(ty*4+i)*132 + kk + k];
#pragma unroll
                    for (int j = 0; j < 4; j++) bb[j] = Ch[(tx*4+j)*17 + k];
#pragma unroll
                    for (int i = 0; i < 4; i++)
#pragma unroll
                        for (int j = 0; j < 4; j++)
                            sacc[i][j] = fmaf(a[i], bb[j], sacc[i][j]);
                }
                __syncthreads();
            }
            float* Sy = Sm + y * (64*65);
#pragma unroll
            for (int i = 0; i < 4; i++)
#pragma unroll
                for (int j = 0; j < 4; j++)
                    Sy[(ty*4+i)*65 + tx*4+j] = sacc[i][j] * SCALE;
        }
        __syncthreads();
        // ---- softmax across y (<=4 values per element)
#pragma unroll
        for (int i = 0; i < 16; i++) {
            int idx = tid + i * 256;
            int r = idx >> 6, c = idx & 63;
            int off = r*65 + c;
            float mx = Sm[off];
            for (int y = 1; y < ny; y++) mx = fmaxf(mx, Sm[y*(64*65) + off]);
            float s = 0.f, ev[4];
            for (int y = 0; y < ny; y++) { ev[y] = expf(Sm[y*(64*65)+off] - mx); s += ev[y]; }
            float inv = 1.f / s;
            for (int y = 0; y < ny; y++) Sm[y*(64*65)+off] = ev[y]*inv;
        }
        __syncthreads();
        // ---- catt: vacc += series_y @ Retrieval_y
        for (int y = 0; y < ny; y++) {
            const float* Rt = g_retr + ((size_t)((b*XX + x)*YY + y)*LL + m0) * EE;
            const float* Sy = Sm + y*(64*65);
            for (int kk = 0; kk < 64; kk += 16) {
#pragma unroll
                for (int i = 0; i < 8; i++) {
                    int idx = tid + i*256;
                    int k = idx >> 7, e = idx & 127;
                    Ch[k*132 + e] = Rt[(size_t)(kk + k)*EE + e];
                }
                __syncthreads();
#pragma unroll
                for (int k = 0; k < 16; k++) {
                    float a[4], bb[8];
#pragma unroll
                    for (int i = 0; i < 4; i++) a[i] = Sy[(ty*4+i)*65 + kk + k];
#pragma unroll
                    for (int j = 0; j < 8; j++) bb[j] = Ch[k*132 + tx*8 + j];
#pragma unroll
                    for (int i = 0; i < 4; i++)
#pragma unroll
                        for (int j = 0; j < 8; j++)
                            vacc[i][j] = fmaf(a[i], bb[j], vacc[i][j]);
                }
                __syncthreads();
            }
        }
        __syncthreads();
    }
    // ---- reduce partial V into g_vpart[b][l][e][x]
#pragma unroll
    for (int i = 0; i < 4; i++) {
        int l = l0 + ty*4 + i;
#pragma unroll
        for (int j = 0; j < 8; j++) {
            int e = tx*8 + j;
            atomicAdd(&g_vpart[(((size_t)b*LL + l)*EE + e)*XX + x], vacc[i][j]);
        }
    }
}

// ---------------- V output: (view of g_vpart) @ Wv^T + bv ----------------
__global__ void __launch_bounds__(256) aa_k_vout(const float* __restrict__ Wv,
                                                 const float* __restrict__ bv,
                                                 float* __restrict__ out)
{
    gemm_nt_tile(g_vpart, 128, Wv, 128, out, 128, 128, 1.0f, bv);
}

// ---------------- series_out == 0.25 everywhere --------------------------
__global__ void __launch_bounds__(256) aa_k_fill(float* __restrict__ p, float v)
{
    p[(size_t)blockIdx.x * 256 + threadIdx.x] = v;
}

// ---------------- prior + sig ---------------------------------------------
__global__ void __launch_bounds__(256) aa_k_prior(const float* __restrict__ sigma,
                                                  float* __restrict__ prior,
                                                  float* __restrict__ sig_out)
{
    int row = blockIdx.x;              // (b*4+h)*1024 + i
    int i = row & 1023;
    int h = (row >> 10) & 3;
    int b = row >> 12;
    float v = sigma[((size_t)b*LL + i)*XX + h];
    float s = sig_transform(v);
    if (threadIdx.x == 0) sig_out[row] = s;

    // replicate ref op order: 1/(C*s) * exp(((-d^2)/2)/s^2)
    float denom = 2.5066282746310002f * s;   // fl32(sqrt(2*pi)) * s
    float coef = 1.0f / denom;               // IEEE f32 divide
    float s2 = s * s;
    float* p = prior + (size_t)row * LL;
    float fi = (float)i;
    for (int j = threadIdx.x; j < LL; j += 256) {
        float d = fabsf(fi - (float)j);
        float d2 = d * d;                    // exact (<= 1023^2 < 2^24)
        float num = -d2 * 0.5f;              // division by 2.0 is exact
        float arg = num / s2;                // IEEE f32 divide, matches ref
        p[j] = coef * expf(arg);
    }
}

// =========================================================================
extern "C" void kernel_launch(void* const* d_in, const int* in_sizes, int n_in,
                              void* d_out, int out_size)
{
    // identify inputs by element count (robust to scalar/bool input handling)
    const float* big[5] = {};
    int nbig = 0;
    const float* sigma = nullptr;
    const float* w[2] = {};
    int nw = 0;
    const float* bias[2] = {};
    int nb = 0;
    for (int i = 0; i < n_in; i++) {
        int sz = in_sizes[i];
        if (sz == BB*LL*XX*EE)      { if (nbig < 5) big[nbig++] = (const float*)d_in[i]; }
        else if (sz == BB*LL*XX)    { sigma = (const float*)d_in[i]; }
        else if (sz == EE*EE)       { if (nw < 2) w[nw++] = (const float*)d_in[i]; }
        else if (sz == EE)          { if (nb < 2) bias[nb++] = (const float*)d_in[i]; }
    }
    const float* query = big[1];
    const float* key_  = big[2];
    const float* value = big[3];
    const float* qplus = big[4];
    const float* Wk = w[0];    const float* bk = bias[0];
    const float* Wv = w[1];    const float* bv = bias[1];

    float* out       = (float*)d_out;
    float* outV      = out;                              // [2,1024,4,128]
    float* outSeries = out + 1048576;                    // [2,4,1024,1024]
    float* outPrior  = out + 1048576 + 8388608;          // [2,4,1024,1024]
    float* outSig    = out + 1048576 + 2*8388608;        // [2,4,1024,1]

    const int smem2 = (64*132 + 4*64*65 + 16*132) * 4;   // 108800 B
    cudaFuncSetAttribute(aa_k_stage2, cudaFuncAttributeMaxDynamicSharedMemorySize, smem2);

    dim3 thr(256);
    aa_k_scores <<<dim3(16,16,8),  thr>>>(query, key_);
    aa_k_softmax<<<dim3(8192),     thr>>>();
    aa_k_retr   <<<dim3(2,16,20),  thr>>>(value);
    aa_k_kplus  <<<dim3(2,16,20),  thr>>>(Wk, bk);
    aa_k_zero_vpart<<<dim3((BB*LL*EE*XX)/256), thr>>>();
    aa_k_stage2 <<<dim3(128*NSLICE), thr, smem2>>>(qplus);
    aa_k_vout   <<<dim3(2,128),    thr>>>(Wv, bv, outV);
    aa_k_fill   <<<dim3(8388608/256), thr>>>(outSeries, 0.25f);
    aa_k_prior  <<<dim3(8192),     thr>>>(sigma, outPrior, outSig);
}

// round 5
// speedup vs baseline: 1.1275x; 1.1275x over previous
#include <cuda_runtime.h>
#include <math.h>

#define BB 2
#define LL 1024
#define XX 4
#define EE 128
#define YY 4
#define SCALE 0.08838834764831845f   // 1/sqrt(128)

// ---------------- scratch (static device globals; no allocation) ----------
__device__ float g_search[BB*XX*LL*LL];        // [b][x][l][s]    32 MB
__device__ float g_retr  [BB*XX*LL*YY*EE];     // [b][x][l][y][e] 16 MB (only y<=x valid)
__device__ float g_qk    [BB*LL*XX*EE];        // q_plus @ Wk      4 MB
__device__ float g_vpart [BB*LL*EE*XX];        // [b][l][e][x]     4 MB

// s = 3^(sigmoid(5v)+1e-5) - 1 via libdevice (bit-matches jax-on-GPU reference)
__device__ __forceinline__ float sig_transform(float v) {
    float t = 5.0f * v;
    float e = expf(-t);
    float sigmoid = 1.0f / (1.0f + e);
    float sg = sigmoid + 1e-5f;
    float p = powf(3.0f, sg);
    return p - 1.0f;
}

// ---------------- NT core: C[64,64] = scale*A·B^T (+bias), k-major smem ----
__device__ __forceinline__ void gemm_nt_core(
    const float* __restrict__ A, int lda,
    const float* __restrict__ B, int ldb,
    float* __restrict__ C, int ldc,
    int K, float scale, const float* __restrict__ bias)
{
    __shared__ float As[16*68];
    __shared__ float Bs[16*68];
    const int tid = threadIdx.x;
    const int tx = tid & 15, ty = tid >> 4;
    const int lr = tid >> 2;          // 0..63
    const int lk = (tid & 3) << 2;    // 0,4,8,12
    const int row0 = blockIdx.y * 64;
    const int col0 = blockIdx.x * 64;
    const float* Ap = A + (size_t)(row0 + lr) * lda + lk;
    const float* Bp = B + (size_t)(col0 + lr) * ldb + lk;
    float acc[4][4] = {};
    for (int kk = 0; kk < K; kk += 16) {
        float4 av = *(const float4*)(Ap + kk);
        float4 bv = *(const float4*)(Bp + kk);
        __syncthreads();
        As[(lk+0)*68+lr]=av.x; As[(lk+1)*68+lr]=av.y;
        As[(lk+2)*68+lr]=av.z; As[(lk+3)*68+lr]=av.w;
        Bs[(lk+0)*68+lr]=bv.x; Bs[(lk+1)*68+lr]=bv.y;
        Bs[(lk+2)*68+lr]=bv.z; Bs[(lk+3)*68+lr]=bv.w;
        __syncthreads();
#pragma unroll
        for (int k = 0; k < 16; k++) {
            float4 a4 = *(const float4*)&As[k*68 + ty*4];
            float4 b4 = *(const float4*)&Bs[k*68 + tx*4];
            float a_[4] = {a4.x, a4.y, a4.z, a4.w};
            float b_[4] = {b4.x, b4.y, b4.z, b4.w};
#pragma unroll
            for (int i = 0; i < 4; i++)
#pragma unroll
                for (int j = 0; j < 4; j++)
                    acc[i][j] = fmaf(a_[i], b_[j], acc[i][j]);
        }
    }
#pragma unroll
    for (int i = 0; i < 4; i++) {
        float4 o;
        o.x = acc[i][0]*scale; o.y = acc[i][1]*scale;
        o.z = acc[i][2]*scale; o.w = acc[i][3]*scale;
        if (bias) {
            o.x += bias[col0+tx*4+0]; o.y += bias[col0+tx*4+1];
            o.z += bias[col0+tx*4+2]; o.w += bias[col0+tx*4+3];
        }
        *(float4*)&C[(size_t)(row0+ty*4+i)*ldc + col0 + tx*4] = o;
    }
}

// ---------------- NN core: C[64,64] = A·B, k-major smem --------------------
__device__ __forceinline__ void gemm_nn_core(
    const float* __restrict__ A, int lda,
    const float* __restrict__ B, int ldb,
    float* __restrict__ C, int ldc, int K)
{
    __shared__ float As[16*68];
    __shared__ float Bs[16*68];
    const int tid = threadIdx.x;
    const int tx = tid & 15, ty = tid >> 4;
    const int lr = tid >> 2;
    const int lk = (tid & 3) << 2;
    const int bk_ = tid >> 4;         // 0..15
    const int bn = (tid & 15) << 2;   // 0..60
    const int row0 = blockIdx.y * 64;
    const int col0 = blockIdx.x * 64;
    const float* Ap = A + (size_t)(row0 + lr) * lda + lk;
    float acc[4][4] = {};
    for (int kk = 0; kk < K; kk += 16) {
        float4 av = *(const float4*)(Ap + kk);
        float4 bv = *(const float4*)&B[(size_t)(kk + bk_) * ldb + col0 + bn];
        __syncthreads();
        As[(lk+0)*68+lr]=av.x; As[(lk+1)*68+lr]=av.y;
        As[(lk+2)*68+lr]=av.z; As[(lk+3)*68+lr]=av.w;
        *(float4*)&Bs[bk_*68 + bn] = bv;
        __syncthreads();
#pragma unroll
        for (int k = 0; k < 16; k++) {
            float4 a4 = *(const float4*)&As[k*68 + ty*4];
            float4 b4 = *(const float4*)&Bs[k*68 + tx*4];
            float a_[4] = {a4.x, a4.y, a4.z, a4.w};
            float b_[4] = {b4.x, b4.y, b4.z, b4.w};
#pragma unroll
            for (int i = 0; i < 4; i++)
#pragma unroll
                for (int j = 0; j < 4; j++)
                    acc[i][j] = fmaf(a_[i], b_[j], acc[i][j]);
        }
    }
#pragma unroll
    for (int i = 0; i < 4; i++) {
        float4 o;
        o.x = acc[i][0]; o.y = acc[i][1]; o.z = acc[i][2]; o.w = acc[i][3];
        *(float4*)&C[(size_t)(row0+ty*4+i)*ldc + col0 + tx*4] = o;
    }
}

// ---------------- stage 1: g_search = scale * Q K^T per (b,x) --------------
__global__ void __launch_bounds__(256) aa_k_scores(const float* __restrict__ q,
                                                   const float* __restrict__ k)
{
    int bz = blockIdx.z;
    int b = bz >> 2, x = bz & 3;
    const float* A = q + ((size_t)b*LL*XX + x) * EE;
    const float* Bm = k + ((size_t)b*LL*XX + x) * EE;
    float* C = g_search + (size_t)bz * LL * LL;
    gemm_nt_core(A, XX*EE, Bm, XX*EE, C, LL, EE, SCALE, nullptr);
}

// ---------------- row softmax over s (in place) ----------------------------
__global__ void __launch_bounds__(256) aa_k_softmax()
{
    size_t row = blockIdx.x;
    float* p = g_search + row * LL;
    int tid = threadIdx.x;
    float v[4];
    float m = -1e30f;
#pragma unroll
    for (int i = 0; i < 4; i++) { v[i] = p[tid + i*256]; m = fmaxf(m, v[i]); }
    __shared__ float red[256];
    red[tid] = m; __syncthreads();
    for (int s = 128; s > 0; s >>= 1) {
        if (tid < s) red[tid] = fmaxf(red[tid], red[tid+s]);
        __syncthreads();
    }
    m = red[0]; __syncthreads();
    float sum = 0.f;
#pragma unroll
    for (int i = 0; i < 4; i++) { v[i] = expf(v[i] - m); sum += v[i]; }
    red[tid] = sum; __syncthreads();
    for (int s = 128; s > 0; s >>= 1) {
        if (tid < s) red[tid] += red[tid+s];
        __syncthreads();
    }
    float inv = 1.f / red[0];
#pragma unroll
    for (int i = 0; i < 4; i++) p[tid + i*256] = v[i] * inv;
}

// ---------------- Retrieval: single pass over Search, all y at once --------
// g_retr[b][x][l][y][e] = sum_s Search[b,x,l,s] * value[b,s,y,e]
__global__ void __launch_bounds__(256) aa_k_retr(const float* __restrict__ val)
{
    int bz = blockIdx.z;
    int b = bz >> 2, x = bz & 3;
    int ny = x + 1;
    if ((int)blockIdx.x * 64 >= ny * EE) return;
    const float* A  = g_search + (size_t)bz * LL * LL;
    const float* Bm = val + (size_t)b * LL * YY * EE;
    float* C = g_retr + (size_t)bz * LL * YY * EE;
    gemm_nn_core(A, LL, Bm, YY*EE, C, YY*EE, LL);
}

// ---------------- qk = q_plus @ Wk (bias bk cancels in softmax over y) ------
__global__ void __launch_bounds__(256) aa_k_qk(const float* __restrict__ qp,
                                               const float* __restrict__ Wk)
{
    gemm_nn_core(qp, EE, Wk, EE, g_qk, EE, EE);
}

// ---------------- zero V partial -------------------------------------------
__global__ void __launch_bounds__(256) aa_k_zero_vpart()
{
    g_vpart[blockIdx.x * 256 + threadIdx.x] = 0.f;
}

// ---------------- fused stage 2: scores -> softmax(Y) -> catt -> V ---------
#define NSLICE 8
__global__ void __launch_bounds__(256, 1) aa_k_stage2()
{
    extern __shared__ float smx[];
    float* Qs = smx;              // [128 e][68]  (qk tile, k-major)
    float* Sm = Qs + 128*68;      // 4 * [64 l][65 m]
    float* Rb = Sm + 4*64*65;     // 8704 floats: scores [e][68 m] / catt [m][132 e]

    int bz = blockIdx.x;
    int slice = bz & (NSLICE - 1);
    int rest = bz >> 3;
    int lt = rest & 15;
    int x  = (rest >> 4) & 3;
    int b  = rest >> 6;
    const int tid = threadIdx.x;
    const int tx = tid & 15, ty = tid >> 4;
    const int lr = tid >> 2;
    const int lk = (tid & 3) << 2;
    const int l0 = lt * 64;
    const int ny = x + 1;

    // load Qs transposed [e][l]
    {
        const float* Qg = g_qk + (((size_t)b*LL + l0 + lr)*XX + x)*EE + lk;
#pragma unroll
        for (int ec = 0; ec < 8; ec++) {
            float4 v = *(const float4*)(Qg + ec*16);
            int e = ec*16 + lk;
            Qs[(e+0)*68+lr]=v.x; Qs[(e+1)*68+lr]=v.y;
            Qs[(e+2)*68+lr]=v.z; Qs[(e+3)*68+lr]=v.w;
        }
    }
    __syncthreads();

    float vacc[4][8] = {};
    const size_t rbase = (size_t)(b*XX + x) * LL * (YY*EE);

    for (int mt = slice*2; mt < slice*2 + 2; mt++) {
        const int m0 = mt * 64;
        // ---- scores S_y[l][m] = sum_e Qs * R^T
        for (int y = 0; y < ny; y++) {
            const float* Rt = g_retr + rbase + (size_t)m0*(YY*EE) + y*EE;
            __syncthreads();
            {
                const float* Rg = Rt + (size_t)lr*(YY*EE) + lk;
#pragma unroll
                for (int ec = 0; ec < 8; ec++) {
                    float4 v = *(const float4*)(Rg + ec*16);
                    int e = ec*16 + lk;
                    Rb[(e+0)*68+lr]=v.x; Rb[(e+1)*68+lr]=v.y;
                    Rb[(e+2)*68+lr]=v.z; Rb[(e+3)*68+lr]=v.w;
                }
            }
            __syncthreads();
            float sacc[4][4] = {};
#pragma unroll 8
            for (int k = 0; k < 128; k++) {
                float4 a4 = *(const float4*)&Qs[k*68 + ty*4];
                float4 b4 = *(const float4*)&Rb[k*68 + tx*4];
                float a_[4] = {a4.x, a4.y, a4.z, a4.w};
                float b_[4] = {b4.x, b4.y, b4.z, b4.w};
#pragma unroll
                for (int i = 0; i < 4; i++)
#pragma unroll
                    for (int j = 0; j < 4; j++)
                        sacc[i][j] = fmaf(a_[i], b_[j], sacc[i][j]);
            }
            float* Sy = Sm + y * (64*65);
#pragma unroll
            for (int i = 0; i < 4; i++)
#pragma unroll
                for (int j = 0; j < 4; j++)
                    Sy[(ty*4+i)*65 + tx*4+j] = sacc[i][j] * SCALE;
        }
        __syncthreads();
        // ---- softmax across y
#pragma unroll
        for (int i = 0; i < 16; i++) {
            int idx = tid + i * 256;
            int r = idx >> 6, c = idx & 63;
            int off = r*65 + c;
            float mx = Sm[off];
            for (int y = 1; y < ny; y++) mx = fmaxf(mx, Sm[y*(64*65) + off]);
            float s = 0.f, ev[4];
            for (int y = 0; y < ny; y++) { ev[y] = expf(Sm[y*(64*65)+off] - mx); s += ev[y]; }
            float inv = 1.f / s;
            for (int y = 0; y < ny; y++) Sm[y*(64*65)+off] = ev[y]*inv;
        }
        __syncthreads();
        // ---- catt: vacc += S_y @ R_y
        for (int y = 0; y < ny; y++) {
            const float* Rt = g_retr + rbase + (size_t)m0*(YY*EE) + y*EE;
#pragma unroll
            for (int i = 0; i < 8; i++) {
                int idx = tid + i*256;
                int m = idx >> 5;
                int e4 = (idx & 31) << 2;
                float4 v = *(const float4*)&Rt[(size_t)m*(YY*EE) + e4];
                *(float4*)&Rb[m*132 + e4] = v;
            }
            __syncthreads();
            const float* Sy = Sm + y*(64*65);
#pragma unroll 4
            for (int k = 0; k < 64; k++) {
                float a_[4];
#pragma unroll
                for (int i = 0; i < 4; i++) a_[i] = Sy[(ty*4+i)*65 + k];
                float4 b0 = *(const float4*)&Rb[k*132 + tx*8];
                float4 b1 = *(const float4*)&Rb[k*132 + tx*8 + 4];
                float b_[8] = {b0.x,b0.y,b0.z,b0.w,b1.x,b1.y,b1.z,b1.w};
#pragma unroll
                for (int i = 0; i < 4; i++)
#pragma unroll
                    for (int j = 0; j < 8; j++)
                        vacc[i][j] = fmaf(a_[i], b_[j], vacc[i][j]);
            }
            __syncthreads();
        }
    }
    // ---- reduce partial V into g_vpart[b][l][e][x]
#pragma unroll
    for (int i = 0; i < 4; i++) {
        int l = l0 + ty*4 + i;
#pragma unroll
        for (int j = 0; j < 8; j++) {
            int e = tx*8 + j;
            atomicAdd(&g_vpart[(((size_t)b*LL + l)*EE + e)*XX + x], vacc[i][j]);
        }
    }
}

// ---------------- V output: g_vpart (viewed [8192,128]) @ Wv^T + bv --------
__global__ void __launch_bounds__(256) aa_k_vout(const float* __restrict__ Wv,
                                                 const float* __restrict__ bv,
                                                 float* __restrict__ out)
{
    gemm_nt_core(g_vpart, EE, Wv, EE, out, EE, EE, 1.0f, bv);
}

// ---------------- series_out == 0.25 everywhere ----------------------------
__global__ void __launch_bounds__(256) aa_k_fill(float* __restrict__ p, float v)
{
    p[(size_t)blockIdx.x * 256 + threadIdx.x] = v;
}

// ---------------- prior + sig ----------------------------------------------
__global__ void __launch_bounds__(256) aa_k_prior(const float* __restrict__ sigma,
                                                  float* __restrict__ prior,
                                                  float* __restrict__ sig_out)
{
    int row = blockIdx.x;
    int i = row & 1023;
    int h = (row >> 10) & 3;
    int b = row >> 12;
    float v = sigma[((size_t)b*LL + i)*XX + h];
    float s = sig_transform(v);
    if (threadIdx.x == 0) sig_out[row] = s;
    float denom = 2.5066282746310002f * s;
    float coef = 1.0f / denom;
    float s2 = s * s;
    float* p = prior + (size_t)row * LL;
    float fi = (float)i;
    for (int j = threadIdx.x; j < LL; j += 256) {
        float d = fabsf(fi - (float)j);
        float d2 = d * d;
        float num = -d2 * 0.5f;
        float arg = num / s2;
        p[j] = coef * expf(arg);
    }
}

// =========================================================================
extern "C" void kernel_launch(void* const* d_in, const int* in_sizes, int n_in,
                              void* d_out, int out_size)
{
    const float* big[5] = {};
    int nbig = 0;
    const float* sigma = nullptr;
    const float* w[2] = {};
    int nw = 0;
    const float* bias[2] = {};
    int nb = 0;
    for (int i = 0; i < n_in; i++) {
        int sz = in_sizes[i];
        if (sz == BB*LL*XX*EE)      { if (nbig < 5) big[nbig++] = (const float*)d_in[i]; }
        else if (sz == BB*LL*XX)    { sigma = (const float*)d_in[i]; }
        else if (sz == EE*EE)       { if (nw < 2) w[nw++] = (const float*)d_in[i]; }
        else if (sz == EE)          { if (nb < 2) bias[nb++] = (const float*)d_in[i]; }
    }
    const float* query = big[1];
    const float* key_  = big[2];
    const float* value = big[3];
    const float* qplus = big[4];
    const float* Wk = w[0];
    const float* Wv = w[1];    const float* bv = bias[1];

    float* out       = (float*)d_out;
    float* outV      = out;
    float* outSeries = out + 1048576;
    float* outPrior  = out + 1048576 + 8388608;
    float* outSig    = out + 1048576 + 2*8388608;

    const int smem2 = (128*68 + 4*64*65 + 8704) * 4;   // 136192 B
    cudaFuncSetAttribute(aa_k_stage2, cudaFuncAttributeMaxDynamicSharedMemorySize, smem2);

    dim3 thr(256);
    aa_k_scores <<<dim3(16,16,8),  thr>>>(query, key_);
    aa_k_softmax<<<dim3(8192),     thr>>>();
    aa_k_retr   <<<dim3(8,16,8),   thr>>>(value);
    aa_k_qk     <<<dim3(2,128),    thr>>>(qplus, Wk);
    aa_k_zero_vpart<<<dim3((BB*LL*EE*XX)/256), thr>>>();
    aa_k_stage2 <<<dim3(128*NSLICE), thr, smem2>>>();
    aa_k_vout   <<<dim3(2,128),    thr>>>(Wv, bv, outV);
    aa_k_fill   <<<dim3(8388608/256), thr>>>(outSeries, 0.25f);
    aa_k_prior  <<<dim3(8192),     thr>>>(sigma, outPrior, outSig);
}

// round 6
// speedup vs baseline: 1.5081x; 1.3375x over previous
#include <cuda_runtime.h>
#include <math.h>

#define BB 2
#define LL 1024
#define XX 4
#define EE 128
#define YY 4
#define SCALE 0.08838834764831845f   // 1/sqrt(128)

// ---------------- scratch (static device globals; no allocation) ----------
__device__ float g_search[BB*XX*LL*LL];        // [b][x][l][s]      32 MB
__device__ float g_retr  [BB*XX*YY*LL*EE];     // [b][x][y][m][e]   16 MB (y<=x valid)
__device__ float g_qk    [BB*LL*XX*EE];        // q_plus @ Wk        4 MB
__device__ float g_s2    [BB*10*LL*LL];        // scores2/series planes 80 MB
__device__ float g_vpart [BB*LL*EE*XX];        // [b][l][e][x]       4 MB

__constant__ int c_xy_x[10] = {0,1,1,2,2,2,3,3,3,3};
__constant__ int c_xy_y[10] = {0,0,1,0,1,2,0,1,2,3};
__constant__ int c_tri[4]  = {0,1,3,6};

// s = 3^(sigmoid(5v)+1e-5) - 1 via libdevice (bit-matches jax-on-GPU reference)
__device__ __forceinline__ float sig_transform(float v) {
    float t = 5.0f * v;
    float e = expf(-t);
    float sigmoid = 1.0f / (1.0f + e);
    float sg = sigmoid + 1e-5f;
    float p = powf(3.0f, sg);
    return p - 1.0f;
}

// ================= bf16-3x tensor-core GEMM machinery ======================
__device__ __forceinline__ unsigned bfbits(float x) {
    unsigned u = __float_as_uint(x);
    return (u + 0x7fffu + ((u >> 16) & 1u)) >> 16;
}
__device__ __forceinline__ float bfval(unsigned b) { return __uint_as_float(b << 16); }
__device__ __forceinline__ void split_pack(float x0, float x1, unsigned &hi, unsigned &lo) {
    unsigned h0 = bfbits(x0), h1 = bfbits(x1);
    unsigned l0 = bfbits(x0 - bfval(h0)), l1 = bfbits(x1 - bfval(h1));
    hi = h0 | (h1 << 16);
    lo = l0 | (l1 << 16);
}
__device__ __forceinline__ void mma_bf16(float (&c)[4],
    unsigned a0, unsigned a1, unsigned a2, unsigned a3,
    unsigned b0, unsigned b1)
{
    asm volatile("mma.sync.aligned.m16n8k16.row.col.f32.bf16.bf16.f32 "
        "{%0,%1,%2,%3},{%4,%5,%6,%7},{%8,%9},{%0,%1,%2,%3};"
        : "+f"(c[0]), "+f"(c[1]), "+f"(c[2]), "+f"(c[3])
        : "r"(a0), "r"(a1), "r"(a2), "r"(a3), "r"(b0), "r"(b1));
}

#define ST 20  // 32-bit words per smem row (16 data + 4 pad -> conflict-free)

// C tile 128x64, block 256 threads (8 warps as 4x2 of 32x32 warp tiles).
// A: row-major m x k (lda). TRANSB=0: B row-major n x k (NT). TRANSB=1: B row-major k x n (NN).
// Accumulates into acc (caller-initialized) -> callable per K-plane.
template<int TRANSB>
__device__ __forceinline__ void mma_core(
    const float* __restrict__ A, int lda,
    const float* __restrict__ B, int ldb,
    int K, float (&acc)[2][4][4])
{
    __shared__ unsigned Ah[128*ST], Al[128*ST], Bh[64*ST], Bl[64*ST];
    const int tid = threadIdx.x;
    const int lane = tid & 31, w = tid >> 5;
    const int g = lane >> 2, tg = lane & 3;
    const int wrow = w >> 1, wcol = w & 1;

    for (int kk = 0; kk < K; kk += 32) {
        __syncthreads();
        { // A tile 128 x 32 -> hi/lo bf16, k-contiguous rows
            int r = tid >> 1, h = tid & 1;
            const float* p = A + (size_t)r*lda + kk + h*16;
            unsigned* dh = Ah + r*ST + h*8;
            unsigned* dl = Al + r*ST + h*8;
#pragma unroll
            for (int j = 0; j < 4; j++) {
                float4 v = *(const float4*)(p + j*4);
                unsigned h0,l0,h1,l1;
                split_pack(v.x, v.y, h0, l0);
                split_pack(v.z, v.w, h1, l1);
                dh[j*2] = h0; dh[j*2+1] = h1;
                dl[j*2] = l0; dl[j*2+1] = l1;
            }
        }
        if (TRANSB) { // B gmem [k][n] 32 x 64 -> smem [n][k]
            int kr = tid >> 3;
            int nb = tid & 7;
            unsigned short* sh = (unsigned short*)Bh;
            unsigned short* sl = (unsigned short*)Bl;
#pragma unroll
            for (int j = 0; j < 8; j++) {
                int n = nb + 8*j;
                float v = B[(size_t)(kk + kr)*ldb + n];
                unsigned hb = bfbits(v);
                unsigned lb = bfbits(v - bfval(hb));
                sh[n*(2*ST) + kr] = (unsigned short)hb;
                sl[n*(2*ST) + kr] = (unsigned short)lb;
            }
        } else {      // B gmem [n][k] 64 x 32
            int r = tid >> 2, q = tid & 3;
            const float* p = B + (size_t)r*ldb + kk + q*8;
            unsigned* dh = Bh + r*ST + q*4;
            unsigned* dl = Bl + r*ST + q*4;
#pragma unroll
            for (int j = 0; j < 2; j++) {
                float4 v = *(const float4*)(p + j*4);
                unsigned h0,l0,h1,l1;
                split_pack(v.x, v.y, h0, l0);
                split_pack(v.z, v.w, h1, l1);
                dh[j*2] = h0; dh[j*2+1] = h1;
                dl[j*2] = l0; dl[j*2+1] = l1;
            }
        }
        __syncthreads();
#pragma unroll
        for (int k16 = 0; k16 < 2; k16++) {
            const int ko = k16*8;
            unsigned ah[2][4], al[2][4], bh[4][2], bl[4][2];
#pragma unroll
            for (int mt = 0; mt < 2; mt++) {
                int m = wrow*32 + mt*16;
                ah[mt][0] = Ah[(m+g  )*ST + tg   + ko];
                ah[mt][1] = Ah[(m+g+8)*ST + tg   + ko];
                ah[mt][2] = Ah[(m+g  )*ST + tg+4 + ko];
                ah[mt][3] = Ah[(m+g+8)*ST + tg+4 + ko];
                al[mt][0] = Al[(m+g  )*ST + tg   + ko];
                al[mt][1] = Al[(m+g+8)*ST + tg   + ko];
                al[mt][2] = Al[(m+g  )*ST + tg+4 + ko];
                al[mt][3] = Al[(m+g+8)*ST + tg+4 + ko];
            }
#pragma unroll
            for (int nt = 0; nt < 4; nt++) {
                int n = wcol*32 + nt*8;
                bh[nt][0] = Bh[(n+g)*ST + tg   + ko];
                bh[nt][1] = Bh[(n+g)*ST + tg+4 + ko];
                bl[nt][0] = Bl[(n+g)*ST + tg   + ko];
                bl[nt][1] = Bl[(n+g)*ST + tg+4 + ko];
            }
#pragma unroll
            for (int mt = 0; mt < 2; mt++)
#pragma unroll
                for (int nt = 0; nt < 4; nt++) {
                    mma_bf16(acc[mt][nt], ah[mt][0],ah[mt][1],ah[mt][2],ah[mt][3], bh[nt][0],bh[nt][1]);
                    mma_bf16(acc[mt][nt], ah[mt][0],ah[mt][1],ah[mt][2],ah[mt][3], bl[nt][0],bl[nt][1]);
                    mma_bf16(acc[mt][nt], al[mt][0],al[mt][1],al[mt][2],al[mt][3], bh[nt][0],bh[nt][1]);
                }
        }
    }
}

__device__ __forceinline__ void epilogue_rowmajor(
    float (&acc)[2][4][4], float* C, int ldc, float scale)
{
    const int lane = threadIdx.x & 31, w = threadIdx.x >> 5;
    const int g = lane >> 2, tg = lane & 3;
    const int wrow = w >> 1, wcol = w & 1;
#pragma unroll
    for (int mt = 0; mt < 2; mt++)
#pragma unroll
        for (int nt = 0; nt < 4; nt++) {
            int r0 = wrow*32 + mt*16 + g;
            int c0 = wcol*32 + nt*8 + 2*tg;
            float2 v0 = {acc[mt][nt][0]*scale, acc[mt][nt][1]*scale};
            float2 v1 = {acc[mt][nt][2]*scale, acc[mt][nt][3]*scale};
            *(float2*)(C + (size_t)r0*ldc + c0) = v0;
            *(float2*)(C + (size_t)(r0+8)*ldc + c0) = v1;
        }
}

// ---------------- fp32 cores kept for tiny GEMMs (qk, vout) ----------------
__device__ __forceinline__ void gemm_nt_core(
    const float* __restrict__ A, int lda,
    const float* __restrict__ B, int ldb,
    float* __restrict__ C, int ldc,
    int K, float scale, const float* __restrict__ bias)
{
    __shared__ float As[16*68];
    __shared__ float Bs[16*68];
    const int tid = threadIdx.x;
    const int tx = tid & 15, ty = tid >> 4;
    const int lr = tid >> 2;
    const int lk = (tid & 3) << 2;
    const int row0 = blockIdx.y * 64;
    const int col0 = blockIdx.x * 64;
    const float* Ap = A + (size_t)(row0 + lr) * lda + lk;
    const float* Bp = B + (size_t)(col0 + lr) * ldb + lk;
    float acc[4][4] = {};
    for (int kk = 0; kk < K; kk += 16) {
        float4 av = *(const float4*)(Ap + kk);
        float4 bv = *(const float4*)(Bp + kk);
        __syncthreads();
        As[(lk+0)*68+lr]=av.x; As[(lk+1)*68+lr]=av.y;
        As[(lk+2)*68+lr]=av.z; As[(lk+3)*68+lr]=av.w;
        Bs[(lk+0)*68+lr]=bv.x; Bs[(lk+1)*68+lr]=bv.y;
        Bs[(lk+2)*68+lr]=bv.z; Bs[(lk+3)*68+lr]=bv.w;
        __syncthreads();
#pragma unroll
        for (int k = 0; k < 16; k++) {
            float4 a4 = *(const float4*)&As[k*68 + ty*4];
            float4 b4 = *(const float4*)&Bs[k*68 + tx*4];
            float a_[4] = {a4.x, a4.y, a4.z, a4.w};
            float b_[4] = {b4.x, b4.y, b4.z, b4.w};
#pragma unroll
            for (int i = 0; i < 4; i++)
#pragma unroll
                for (int j = 0; j < 4; j++)
                    acc[i][j] = fmaf(a_[i], b_[j], acc[i][j]);
        }
    }
#pragma unroll
    for (int i = 0; i < 4; i++) {
        float4 o;
        o.x = acc[i][0]*scale; o.y = acc[i][1]*scale;
        o.z = acc[i][2]*scale; o.w = acc[i][3]*scale;
        if (bias) {
            o.x += bias[col0+tx*4+0]; o.y += bias[col0+tx*4+1];
            o.z += bias[col0+tx*4+2]; o.w += bias[col0+tx*4+3];
        }
        *(float4*)&C[(size_t)(row0+ty*4+i)*ldc + col0 + tx*4] = o;
    }
}

__device__ __forceinline__ void gemm_nn_core(
    const float* __restrict__ A, int lda,
    const float* __restrict__ B, int ldb,
    float* __restrict__ C, int ldc, int K)
{
    __shared__ float As[16*68];
    __shared__ float Bs[16*68];
    const int tid = threadIdx.x;
    const int tx = tid & 15, ty = tid >> 4;
    const int lr = tid >> 2;
    const int lk = (tid & 3) << 2;
    const int bk_ = tid >> 4;
    const int bn = (tid & 15) << 2;
    const int row0 = blockIdx.y * 64;
    const int col0 = blockIdx.x * 64;
    const float* Ap = A + (size_t)(row0 + lr) * lda + lk;
    float acc[4][4] = {};
    for (int kk = 0; kk < K; kk += 16) {
        float4 av = *(const float4*)(Ap + kk);
        float4 bv = *(const float4*)&B[(size_t)(kk + bk_) * ldb + col0 + bn];
        __syncthreads();
        As[(lk+0)*68+lr]=av.x; As[(lk+1)*68+lr]=av.y;
        As[(lk+2)*68+lr]=av.z; As[(lk+3)*68+lr]=av.w;
        *(float4*)&Bs[bk_*68 + bn] = bv;
        __syncthreads();
#pragma unroll
        for (int k = 0; k < 16; k++) {
            float4 a4 = *(const float4*)&As[k*68 + ty*4];
            float4 b4 = *(const float4*)&Bs[k*68 + tx*4];
            float a_[4] = {a4.x, a4.y, a4.z, a4.w};
            float b_[4] = {b4.x, b4.y, b4.z, b4.w};
#pragma unroll
            for (int i = 0; i < 4; i++)
#pragma unroll
                for (int j = 0; j < 4; j++)
                    acc[i][j] = fmaf(a_[i], b_[j], acc[i][j]);
        }
    }
#pragma unroll
    for (int i = 0; i < 4; i++) {
        float4 o;
        o.x = acc[i][0]; o.y = acc[i][1]; o.z = acc[i][2]; o.w = acc[i][3];
        *(float4*)&C[(size_t)(row0+ty*4+i)*ldc + col0 + tx*4] = o;
    }
}

// ================= kernels ==================================================

// stage 1 scores: g_search = scale * Q K^T, tensor core
__global__ void __launch_bounds__(256) aa_t_scores1(const float* __restrict__ q,
                                                    const float* __restrict__ k)
{
    int bz = blockIdx.z, b = bz >> 2, x = bz & 3;
    const float* A = q + ((size_t)b*4096 + x)*128 + (size_t)blockIdx.y*128*512;
    const float* B = k + ((size_t)b*4096 + x)*128 + (size_t)blockIdx.x*64*512;
    float acc[2][4][4] = {};
    mma_core<0>(A, 512, B, 512, 128, acc);
    float* C = g_search + (size_t)bz*LL*LL + (size_t)blockIdx.y*128*1024 + blockIdx.x*64;
    epilogue_rowmajor(acc, C, 1024, SCALE);
}

// row softmax over s (in place)
__global__ void __launch_bounds__(256) aa_k_softmax()
{
    size_t row = blockIdx.x;
    float* p = g_search + row * LL;
    int tid = threadIdx.x;
    float v[4];
    float m = -1e30f;
#pragma unroll
    for (int i = 0; i < 4; i++) { v[i] = p[tid + i*256]; m = fmaxf(m, v[i]); }
    __shared__ float red[256];
    red[tid] = m; __syncthreads();
    for (int s = 128; s > 0; s >>= 1) {
        if (tid < s) red[tid] = fmaxf(red[tid], red[tid+s]);
        __syncthreads();
    }
    m = red[0]; __syncthreads();
    float sum = 0.f;
#pragma unroll
    for (int i = 0; i < 4; i++) { v[i] = expf(v[i] - m); sum += v[i]; }
    red[tid] = sum; __syncthreads();
    for (int s = 128; s > 0; s >>= 1) {
        if (tid < s) red[tid] += red[tid+s];
        __syncthreads();
    }
    float inv = 1.f / red[0];
#pragma unroll
    for (int i = 0; i < 4; i++) p[tid + i*256] = v[i] * inv;
}

// Retrieval planes: g_retr[b][x][y][m][e] = Search @ value, tensor core (NN)
__global__ void __launch_bounds__(256) aa_t_retr(const float* __restrict__ val)
{
    int bz = blockIdx.z, b = bz >> 2, x = bz & 3;
    int n0 = blockIdx.x * 64;
    if (n0 >= (x + 1) * 128) return;
    const float* A = g_search + (size_t)bz*LL*LL + (size_t)blockIdx.y*128*1024;
    const float* B = val + (size_t)b*1024*512 + n0;
    float acc[2][4][4] = {};
    mma_core<1>(A, 1024, B, 512, 1024, acc);
    int y = n0 >> 7;
    float* C = g_retr + ((size_t)(bz*4 + y))*1024*128
             + (size_t)blockIdx.y*128*128 + (n0 & 127);
    epilogue_rowmajor(acc, C, 128, 1.0f);
}

// qk = q_plus @ Wk (bias bk cancels in softmax over y) — fp32, tiny
__global__ void __launch_bounds__(256) aa_k_qk(const float* __restrict__ qp,
                                               const float* __restrict__ Wk)
{
    gemm_nn_core(qp, EE, Wk, EE, g_qk, EE, EE);
}

// stage-2 scores planes: g_s2[plane][l][m] = scale * qk · R^T (NT, tensor)
__global__ void __launch_bounds__(256) aa_t_scores2()
{
    int t = blockIdx.z, b = t / 10, u = t % 10;
    int x = c_xy_x[u], y = c_xy_y[u];
    const float* A = g_qk + ((size_t)b*4096 + x)*128 + (size_t)blockIdx.y*128*512;
    const float* B = g_retr + ((size_t)((b*4 + x)*4 + y))*1024*128
                   + (size_t)blockIdx.x*64*128;
    float acc[2][4][4] = {};
    mma_core<0>(A, 512, B, 128, 128, acc);
    float* C = g_s2 + ((size_t)(b*10 + u))*1048576
             + (size_t)blockIdx.y*128*1024 + blockIdx.x*64;
    epilogue_rowmajor(acc, C, 1024, SCALE);
}

// softmax over y across planes (in place -> series)
__global__ void __launch_bounds__(256) aa_k_softmax2()
{
    int blk = blockIdx.x;
    int l = blk & 1023;
    int x = (blk >> 10) & 3;
    int b = blk >> 12;
    int ny = x + 1;
    size_t pbase = ((size_t)(b*10 + c_tri[x]))*1048576 + (size_t)l*1024;
    for (int m = threadIdx.x; m < 1024; m += 256) {
        float v[4];
        float mx = -1e30f;
#pragma unroll
        for (int y = 0; y < 4; y++) {
            v[y] = (y < ny) ? g_s2[pbase + (size_t)y*1048576 + m] : -1e30f;
            mx = fmaxf(mx, v[y]);
        }
        float s = 0.f;
#pragma unroll
        for (int y = 0; y < 4; y++) { v[y] = expf(v[y] - mx); if (y < ny) s += v[y]; }
        float inv = 1.f / s;
#pragma unroll
        for (int y = 0; y < 4; y++)
            if (y < ny) g_s2[pbase + (size_t)y*1048576 + m] = v[y] * inv;
    }
}

// catt: V[b,l,e,x] = sum_y S_y @ R_y  (NN, tensor, accumulate across planes)
__global__ void __launch_bounds__(256) aa_t_catt()
{
    int bz = blockIdx.z, b = bz >> 2, x = bz & 3, ny = x + 1;
    float acc[2][4][4] = {};
    for (int y = 0; y < ny; y++) {
        const float* A = g_s2 + ((size_t)(b*10 + c_tri[x] + y))*1048576
                       + (size_t)blockIdx.y*128*1024;
        const float* B = g_retr + ((size_t)(bz*4 + y))*1024*128 + blockIdx.x*64;
        mma_core<1>(A, 1024, B, 128, 1024, acc);
    }
    const int lane = threadIdx.x & 31, w = threadIdx.x >> 5;
    const int g = lane >> 2, tg = lane & 3;
    const int wrow = w >> 1, wcol = w & 1;
    const int l0 = blockIdx.y*128, e0 = blockIdx.x*64;
#pragma unroll
    for (int mt = 0; mt < 2; mt++)
#pragma unroll
        for (int nt = 0; nt < 4; nt++) {
            int r = l0 + wrow*32 + mt*16 + g;
            int c = e0 + wcol*32 + nt*8 + 2*tg;
            g_vpart[(((size_t)b*1024 + r  )*128 + c  )*4 + x] = acc[mt][nt][0];
            g_vpart[(((size_t)b*1024 + r  )*128 + c+1)*4 + x] = acc[mt][nt][1];
            g_vpart[(((size_t)b*1024 + r+8)*128 + c  )*4 + x] = acc[mt][nt][2];
            g_vpart[(((size_t)b*1024 + r+8)*128 + c+1)*4 + x] = acc[mt][nt][3];
        }
}

// V output: g_vpart (viewed [8192,128]) @ Wv^T + bv — fp32, tiny
__global__ void __launch_bounds__(256) aa_k_vout(const float* __restrict__ Wv,
                                                 const float* __restrict__ bv,
                                                 float* __restrict__ out)
{
    gemm_nt_core(g_vpart, EE, Wv, EE, out, EE, EE, 1.0f, bv);
}

// series_out == 0.25 everywhere
__global__ void __launch_bounds__(256) aa_k_fill(float* __restrict__ p, float v)
{
    p[(size_t)blockIdx.x * 256 + threadIdx.x] = v;
}

// prior + sig (bit-exact libdevice path — DO NOT CHANGE)
__global__ void __launch_bounds__(256) aa_k_prior(const float* __restrict__ sigma,
                                                  float* __restrict__ prior,
                                                  float* __restrict__ sig_out)
{
    int row = blockIdx.x;
    int i = row & 1023;
    int h = (row >> 10) & 3;
    int b = row >> 12;
    float v = sigma[((size_t)b*LL + i)*XX + h];
    float s = sig_transform(v);
    if (threadIdx.x == 0) sig_out[row] = s;
    float denom = 2.5066282746310002f * s;
    float coef = 1.0f / denom;
    float s2 = s * s;
    float* p = prior + (size_t)row * LL;
    float fi = (float)i;
    for (int j = threadIdx.x; j < LL; j += 256) {
        float d = fabsf(fi - (float)j);
        float d2 = d * d;
        float num = -d2 * 0.5f;
        float arg = num / s2;
        p[j] = coef * expf(arg);
    }
}

// =========================================================================
extern "C" void kernel_launch(void* const* d_in, const int* in_sizes, int n_in,
                              void* d_out, int out_size)
{
    const float* big[5] = {};
    int nbig = 0;
    const float* sigma = nullptr;
    const float* w[2] = {};
    int nw = 0;
    const float* bias[2] = {};
    int nb = 0;
    for (int i = 0; i < n_in; i++) {
        int sz = in_sizes[i];
        if (sz == BB*LL*XX*EE)      { if (nbig < 5) big[nbig++] = (const float*)d_in[i]; }
        else if (sz == BB*LL*XX)    { sigma = (const float*)d_in[i]; }
        else if (sz == EE*EE)       { if (nw < 2) w[nw++] = (const float*)d_in[i]; }
        else if (sz == EE)          { if (nb < 2) bias[nb++] = (const float*)d_in[i]; }
    }
    const float* query = big[1];
    const float* key_  = big[2];
    const float* value = big[3];
    const float* qplus = big[4];
    const float* Wk = w[0];
    const float* Wv = w[1];    const float* bv = bias[1];

    float* out       = (float*)d_out;
    float* outV      = out;
    float* outSeries = out + 1048576;
    float* outPrior  = out + 1048576 + 8388608;
    float* outSig    = out + 1048576 + 2*8388608;

    dim3 thr(256);
    aa_t_scores1<<<dim3(16,8,8),   thr>>>(query, key_);
    aa_k_softmax<<<dim3(8192),     thr>>>();
    aa_t_retr   <<<dim3(8,8,8),    thr>>>(value);
    aa_k_qk     <<<dim3(2,128),    thr>>>(qplus, Wk);
    aa_t_scores2<<<dim3(16,8,20),  thr>>>();
    aa_k_softmax2<<<dim3(8192),    thr>>>();
    aa_t_catt   <<<dim3(2,8,8),    thr>>>();
    aa_k_vout   <<<dim3(2,128),    thr>>>(Wv, bv, outV);
    aa_k_fill   <<<dim3(8388608/256), thr>>>(outSeries, 0.25f);
    aa_k_prior  <<<dim3(8192),     thr>>>(sigma, outPrior, outSig);
}

// round 7
// speedup vs baseline: 1.5836x; 1.0501x over previous
#include <cuda_runtime.h>
#include <math.h>

#define BB 2
#define LL 1024
#define XX 4
#define EE 128
#define YY 4
#define SCALE 0.08838834764831845f   // 1/sqrt(128)

typedef unsigned short ushort_t;

// ---------------- scratch (static device globals) --------------------------
__device__ float g_search[8*1024*1024];                 // stage1 scores fp32  32 MB
__device__ float g_s2    [2*10*1024*1024];              // stage2 scores fp32  80 MB
__device__ float g_vpart [BB*LL*EE*XX];                 // [b][l][e][x]         4 MB

__device__ __align__(16) ushort_t g_qh [2*1024*4*128], g_ql [2*1024*4*128];
__device__ __align__(16) ushort_t g_kh [2*1024*4*128], g_kl [2*1024*4*128];
__device__ __align__(16) ushort_t g_vh [2*1024*512],   g_vl [2*1024*512];
__device__ __align__(16) ushort_t g_qph[2*1024*4*128], g_qpl[2*1024*4*128];
__device__ __align__(16) ushort_t g_wkh[128*128],      g_wkl[128*128];
__device__ __align__(16) ushort_t g_sh [8*1024*1024],  g_sl [8*1024*1024];   // Search bf16
__device__ __align__(16) ushort_t g_qkh[2*1024*4*128], g_qkl[2*1024*4*128];
__device__ __align__(16) ushort_t g_rh [2*4*4*1024*128], g_rl[2*4*4*1024*128];
__device__ __align__(16) ushort_t g_s2h[2*10*1024*1024], g_s2l[2*10*1024*1024];

__constant__ int c_xy_x[10] = {0,1,1,2,2,2,3,3,3,3};
__constant__ int c_xy_y[10] = {0,0,1,0,1,2,0,1,2,3};
__constant__ int c_tri[4]  = {0,1,3,6};

// libdevice path — bit-matches jax-on-GPU reference. DO NOT CHANGE.
__device__ __forceinline__ float sig_transform(float v) {
    float t = 5.0f * v;
    float e = expf(-t);
    float sigmoid = 1.0f / (1.0f + e);
    float sg = sigmoid + 1e-5f;
    float p = powf(3.0f, sg);
    return p - 1.0f;
}

// ================= bf16 split helpers =======================================
__device__ __forceinline__ unsigned bfbits(float x) {
    unsigned u = __float_as_uint(x);
    return (u + 0x7fffu + ((u >> 16) & 1u)) >> 16;
}
__device__ __forceinline__ float bfval(unsigned b) { return __uint_as_float(b << 16); }
__device__ __forceinline__ void split_pack(float x0, float x1, unsigned &hi, unsigned &lo) {
    unsigned h0 = bfbits(x0), h1 = bfbits(x1);
    unsigned l0 = bfbits(x0 - bfval(h0)), l1 = bfbits(x1 - bfval(h1));
    hi = h0 | (h1 << 16);
    lo = l0 | (l1 << 16);
}
__device__ __forceinline__ void mma_bf16(float (&c)[4],
    unsigned a0, unsigned a1, unsigned a2, unsigned a3,
    unsigned b0, unsigned b1)
{
    asm volatile("mma.sync.aligned.m16n8k16.row.col.f32.bf16.bf16.f32 "
        "{%0,%1,%2,%3},{%4,%5,%6,%7},{%8,%9},{%0,%1,%2,%3};"
        : "+f"(c[0]), "+f"(c[1]), "+f"(c[2]), "+f"(c[3])
        : "r"(a0), "r"(a1), "r"(a2), "r"(a3), "r"(b0), "r"(b1));
}

#define ST 20  // unsigned words per smem row (16 data + 4 pad)

// C tile 128x64, 256 threads (8 warps = 4x2 grid of 32x32 warp tiles).
// Operands are PRE-SPLIT bf16 hi/lo in gmem. lda/ldb in bf16 elements.
// TRANSB=0: B is [n][k] row-major (NT). TRANSB=1: B is [k][n] row-major (NN).
template<int TRANSB>
__device__ __forceinline__ void mma_core(
    const ushort_t* __restrict__ Ahg, const ushort_t* __restrict__ Alg, int lda,
    const ushort_t* __restrict__ Bhg, const ushort_t* __restrict__ Blg, int ldb,
    int K, float (&acc)[2][4][4])
{
    __shared__ unsigned Ah[128*ST], Al[128*ST], Bh[64*ST], Bl[64*ST];
    const int tid = threadIdx.x;
    const int lane = tid & 31, w = tid >> 5;
    const int g = lane >> 2, tg = lane & 3;
    const int wrow = w >> 1, wcol = w & 1;

    const int ar = tid >> 1, ah_ = tid & 1;        // A: 128 rows, 2 thr/row
    const int br = tid >> 2, bq = tid & 3;          // B NT: 64 rows, 4 thr/row
    const int kr = tid >> 3, np = tid & 7;          // B NN transpose

    for (int kk = 0; kk < K; kk += 32) {
        const ushort_t* pa = Ahg + (size_t)ar*lda + kk + ah_*16;
        const ushort_t* pl = Alg + (size_t)ar*lda + kk + ah_*16;
        uint4 a0 = *(const uint4*)pa, a1 = *(const uint4*)(pa+8);
        uint4 l0 = *(const uint4*)pl, l1 = *(const uint4*)(pl+8);
        uint4 b0, b1, m0, m1;
        unsigned bt[4], lt[4];
        if (TRANSB) {
#pragma unroll
            for (int j = 0; j < 4; j++) {
                int n2 = np + 8*j;
                bt[j] = *(const unsigned*)(Bhg + (size_t)(kk+kr)*ldb + 2*n2);
                lt[j] = *(const unsigned*)(Blg + (size_t)(kk+kr)*ldb + 2*n2);
            }
        } else {
            const ushort_t* pb = Bhg + (size_t)br*ldb + kk + bq*8;
            const ushort_t* pm = Blg + (size_t)br*ldb + kk + bq*8;
            b0 = *(const uint4*)pb;
            m0 = *(const uint4*)pm;
        }
        __syncthreads();
        *(uint4*)&Ah[ar*ST + ah_*8]     = a0;
        *(uint4*)&Ah[ar*ST + ah_*8 + 4] = a1;
        *(uint4*)&Al[ar*ST + ah_*8]     = l0;
        *(uint4*)&Al[ar*ST + ah_*8 + 4] = l1;
        if (TRANSB) {
            ushort_t* sh = (ushort_t*)Bh;
            ushort_t* sl = (ushort_t*)Bl;
#pragma unroll
            for (int j = 0; j < 4; j++) {
                int n = 2*(np + 8*j);
                sh[ n   *(2*ST) + kr] = (ushort_t)(bt[j] & 0xffff);
                sh[(n+1)*(2*ST) + kr] = (ushort_t)(bt[j] >> 16);
                sl[ n   *(2*ST) + kr] = (ushort_t)(lt[j] & 0xffff);
                sl[(n+1)*(2*ST) + kr] = (ushort_t)(lt[j] >> 16);
            }
        } else {
            *(uint4*)&Bh[br*ST + bq*4] = b0;
            *(uint4*)&Bl[br*ST + bq*4] = m0;
        }
        __syncthreads();
#pragma unroll
        for (int k16 = 0; k16 < 2; k16++) {
            const int ko = k16*8;
            unsigned ah[2][4], al[2][4], bh[4][2], bl[4][2];
#pragma unroll
            for (int mt = 0; mt < 2; mt++) {
                int m = wrow*32 + mt*16;
                ah[mt][0] = Ah[(m+g  )*ST + tg   + ko];
                ah[mt][1] = Ah[(m+g+8)*ST + tg   + ko];
                ah[mt][2] = Ah[(m+g  )*ST + tg+4 + ko];
                ah[mt][3] = Ah[(m+g+8)*ST + tg+4 + ko];
                al[mt][0] = Al[(m+g  )*ST + tg   + ko];
                al[mt][1] = Al[(m+g+8)*ST + tg   + ko];
                al[mt][2] = Al[(m+g  )*ST + tg+4 + ko];
                al[mt][3] = Al[(m+g+8)*ST + tg+4 + ko];
            }
#pragma unroll
            for (int nt = 0; nt < 4; nt++) {
                int n = wcol*32 + nt*8;
                bh[nt][0] = Bh[(n+g)*ST + tg   + ko];
                bh[nt][1] = Bh[(n+g)*ST + tg+4 + ko];
                bl[nt][0] = Bl[(n+g)*ST + tg   + ko];
                bl[nt][1] = Bl[(n+g)*ST + tg+4 + ko];
            }
#pragma unroll
            for (int mt = 0; mt < 2; mt++)
#pragma unroll
                for (int nt = 0; nt < 4; nt++) {
                    mma_bf16(acc[mt][nt], ah[mt][0],ah[mt][1],ah[mt][2],ah[mt][3], bh[nt][0],bh[nt][1]);
                    mma_bf16(acc[mt][nt], ah[mt][0],ah[mt][1],ah[mt][2],ah[mt][3], bl[nt][0],bl[nt][1]);
                    mma_bf16(acc[mt][nt], al[mt][0],al[mt][1],al[mt][2],al[mt][3], bh[nt][0],bh[nt][1]);
                }
        }
    }
}

__device__ __forceinline__ void epilogue_f32(
    float (&acc)[2][4][4], float* C, int ldc, float scale)
{
    const int lane = threadIdx.x & 31, w = threadIdx.x >> 5;
    const int g = lane >> 2, tg = lane & 3;
    const int wrow = w >> 1, wcol = w & 1;
#pragma unroll
    for (int mt = 0; mt < 2; mt++)
#pragma unroll
        for (int nt = 0; nt < 4; nt++) {
            int r0 = wrow*32 + mt*16 + g;
            int c0 = wcol*32 + nt*8 + 2*tg;
            float2 v0 = {acc[mt][nt][0]*scale, acc[mt][nt][1]*scale};
            float2 v1 = {acc[mt][nt][2]*scale, acc[mt][nt][3]*scale};
            *(float2*)(C + (size_t)r0*ldc + c0) = v0;
            *(float2*)(C + (size_t)(r0+8)*ldc + c0) = v1;
        }
}

__device__ __forceinline__ void epilogue_bf16(
    float (&acc)[2][4][4], ushort_t* Ch, ushort_t* Cl, int ldc)
{
    const int lane = threadIdx.x & 31, w = threadIdx.x >> 5;
    const int g = lane >> 2, tg = lane & 3;
    const int wrow = w >> 1, wcol = w & 1;
#pragma unroll
    for (int mt = 0; mt < 2; mt++)
#pragma unroll
        for (int nt = 0; nt < 4; nt++) {
            int r0 = wrow*32 + mt*16 + g;
            int c0 = wcol*32 + nt*8 + 2*tg;
            unsigned h, l;
            split_pack(acc[mt][nt][0], acc[mt][nt][1], h, l);
            *(unsigned*)(Ch + (size_t)r0*ldc + c0) = h;
            *(unsigned*)(Cl + (size_t)r0*ldc + c0) = l;
            split_pack(acc[mt][nt][2], acc[mt][nt][3], h, l);
            *(unsigned*)(Ch + (size_t)(r0+8)*ldc + c0) = h;
            *(unsigned*)(Cl + (size_t)(r0+8)*ldc + c0) = l;
        }
}

// ---------------- fp32 NT core (vout only) ---------------------------------
__device__ __forceinline__ void gemm_nt_core(
    const float* __restrict__ A, int lda,
    const float* __restrict__ B, int ldb,
    float* __restrict__ C, int ldc,
    int K, float scale, const float* __restrict__ bias)
{
    __shared__ float As[16*68];
    __shared__ float Bs[16*68];
    const int tid = threadIdx.x;
    const int tx = tid & 15, ty = tid >> 4;
    const int lr = tid >> 2;
    const int lk = (tid & 3) << 2;
    const int row0 = blockIdx.y * 64;
    const int col0 = blockIdx.x * 64;
    const float* Ap = A + (size_t)(row0 + lr) * lda + lk;
    const float* Bp = B + (size_t)(col0 + lr) * ldb + lk;
    float acc[4][4] = {};
    for (int kk = 0; kk < K; kk += 16) {
        float4 av = *(const float4*)(Ap + kk);
        float4 bv = *(const float4*)(Bp + kk);
        __syncthreads();
        As[(lk+0)*68+lr]=av.x; As[(lk+1)*68+lr]=av.y;
        As[(lk+2)*68+lr]=av.z; As[(lk+3)*68+lr]=av.w;
        Bs[(lk+0)*68+lr]=bv.x; Bs[(lk+1)*68+lr]=bv.y;
        Bs[(lk+2)*68+lr]=bv.z; Bs[(lk+3)*68+lr]=bv.w;
        __syncthreads();
#pragma unroll
        for (int k = 0; k < 16; k++) {
            float4 a4 = *(const float4*)&As[k*68 + ty*4];
            float4 b4 = *(const float4*)&Bs[k*68 + tx*4];
            float a_[4] = {a4.x, a4.y, a4.z, a4.w};
            float b_[4] = {b4.x, b4.y, b4.z, b4.w};
#pragma unroll
            for (int i = 0; i < 4; i++)
#pragma unroll
                for (int j = 0; j < 4; j++)
                    acc[i][j] = fmaf(a_[i], b_[j], acc[i][j]);
        }
    }
#pragma unroll
    for (int i = 0; i < 4; i++) {
        float4 o;
        o.x = acc[i][0]*scale + bias[col0+tx*4+0];
        o.y = acc[i][1]*scale + bias[col0+tx*4+1];
        o.z = acc[i][2]*scale + bias[col0+tx*4+2];
        o.w = acc[i][3]*scale + bias[col0+tx*4+3];
        *(float4*)&C[(size_t)(row0+ty*4+i)*ldc + col0 + tx*4] = o;
    }
}

// ================= kernels ==================================================

// split fp32 inputs -> bf16 hi/lo
__global__ void __launch_bounds__(256) aa_cvt(
    const float* __restrict__ q, const float* __restrict__ k,
    const float* __restrict__ val, const float* __restrict__ qp,
    const float* __restrict__ Wk)
{
    const float* src; ushort_t *dh, *dl; int n;
    switch (blockIdx.y) {
        case 0: src = q;   dh = g_qh;  dl = g_ql;  n = 1048576; break;
        case 1: src = k;   dh = g_kh;  dl = g_kl;  n = 1048576; break;
        case 2: src = val; dh = g_vh;  dl = g_vl;  n = 1048576; break;
        case 3: src = qp;  dh = g_qph; dl = g_qpl; n = 1048576; break;
        default:src = Wk;  dh = g_wkh; dl = g_wkl; n = 16384;   break;
    }
    int i = (blockIdx.x * 256 + threadIdx.x) * 4;
    if (i >= n) return;
    float4 v = *(const float4*)(src + i);
    unsigned h0,l0,h1,l1;
    split_pack(v.x, v.y, h0, l0);
    split_pack(v.z, v.w, h1, l1);
    *(uint2*)(dh + i) = make_uint2(h0, h1);
    *(uint2*)(dl + i) = make_uint2(l0, l1);
}

// stage 1 scores: g_search = scale * Q K^T
__global__ void __launch_bounds__(256) aa_t_scores1()
{
    int bz = blockIdx.z, b = bz >> 2, x = bz & 3;
    size_t qoff = (size_t)b*524288 + x*128;
    const ushort_t* Ah = g_qh + qoff + (size_t)blockIdx.y*128*512;
    const ushort_t* Al = g_ql + qoff + (size_t)blockIdx.y*128*512;
    const ushort_t* Bh = g_kh + qoff + (size_t)blockIdx.x*64*512;
    const ushort_t* Bl = g_kl + qoff + (size_t)blockIdx.x*64*512;
    float acc[2][4][4] = {};
    mma_core<0>(Ah, Al, 512, Bh, Bl, 512, 128, acc);
    float* C = g_search + (size_t)bz*1048576 + (size_t)blockIdx.y*128*1024 + blockIdx.x*64;
    epilogue_f32(acc, C, 1024, SCALE);
}

// row softmax over s; emits bf16 hi/lo Search
__global__ void __launch_bounds__(256) aa_k_softmax()
{
    size_t row = blockIdx.x;
    const float* p = g_search + row * 1024;
    int tid = threadIdx.x;
    float4 v4 = *(const float4*)(p + tid*4);
    float v[4] = {v4.x, v4.y, v4.z, v4.w};
    float m = fmaxf(fmaxf(v[0], v[1]), fmaxf(v[2], v[3]));
    __shared__ float red[256];
    red[tid] = m; __syncthreads();
    for (int s = 128; s > 0; s >>= 1) {
        if (tid < s) red[tid] = fmaxf(red[tid], red[tid+s]);
        __syncthreads();
    }
    m = red[0]; __syncthreads();
    float sum = 0.f;
#pragma unroll
    for (int i = 0; i < 4; i++) { v[i] = expf(v[i] - m); sum += v[i]; }
    red[tid] = sum; __syncthreads();
    for (int s = 128; s > 0; s >>= 1) {
        if (tid < s) red[tid] += red[tid+s];
        __syncthreads();
    }
    float inv = 1.f / red[0];
    unsigned h0,l0,h1,l1;
    split_pack(v[0]*inv, v[1]*inv, h0, l0);
    split_pack(v[2]*inv, v[3]*inv, h1, l1);
    *(uint2*)(g_sh + row*1024 + tid*4) = make_uint2(h0, h1);
    *(uint2*)(g_sl + row*1024 + tid*4) = make_uint2(l0, l1);
}

// Retrieval planes (NN): out bf16 hi/lo g_r[plane][m][e]
__global__ void __launch_bounds__(256) aa_t_retr()
{
    int bz = blockIdx.z, b = bz >> 2, x = bz & 3;
    int n0 = blockIdx.x * 64;
    if (n0 >= (x + 1) * 128) return;
    const ushort_t* Ah = g_sh + (size_t)bz*1048576 + (size_t)blockIdx.y*128*1024;
    const ushort_t* Al = g_sl + (size_t)bz*1048576 + (size_t)blockIdx.y*128*1024;
    const ushort_t* Bh = g_vh + (size_t)b*524288 + n0;
    const ushort_t* Bl = g_vl + (size_t)b*524288 + n0;
    float acc[2][4][4] = {};
    mma_core<1>(Ah, Al, 1024, Bh, Bl, 512, 1024, acc);
    int y = n0 >> 7;
    size_t coff = ((size_t)(bz*4 + y))*131072 + (size_t)blockIdx.y*128*128 + (n0 & 127);
    epilogue_bf16(acc, g_rh + coff, g_rl + coff, 128);
}

// qk = q_plus @ Wk (NN, bias cancels in softmax) -> bf16 hi/lo
__global__ void __launch_bounds__(256) aa_t_qk()
{
    const ushort_t* Ah = g_qph + (size_t)blockIdx.y*128*128;
    const ushort_t* Al = g_qpl + (size_t)blockIdx.y*128*128;
    float acc[2][4][4] = {};
    mma_core<1>(Ah, Al, 128, g_wkh + blockIdx.x*64, g_wkl + blockIdx.x*64, 128, 128, acc);
    size_t coff = (size_t)blockIdx.y*128*128 + blockIdx.x*64;
    epilogue_bf16(acc, g_qkh + coff, g_qkl + coff, 128);
}

// stage-2 scores planes (NT): g_s2[plane] = scale * qk · R^T
__global__ void __launch_bounds__(256) aa_t_scores2()
{
    int t = blockIdx.z, b = t / 10, u = t % 10;
    int x = c_xy_x[u], y = c_xy_y[u];
    size_t aoff = (size_t)b*524288 + x*128 + (size_t)blockIdx.y*128*512;
    size_t boff = ((size_t)((b*4 + x)*4 + y))*131072 + (size_t)blockIdx.x*64*128;
    float acc[2][4][4] = {};
    mma_core<0>(g_qkh + aoff, g_qkl + aoff, 512, g_rh + boff, g_rl + boff, 128, 128, acc);
    float* C = g_s2 + ((size_t)(b*10 + u))*1048576
             + (size_t)blockIdx.y*128*1024 + blockIdx.x*64;
    epilogue_f32(acc, C, 1024, SCALE);
}

// softmax over y across planes -> series bf16 hi/lo
__global__ void __launch_bounds__(256) aa_k_softmax2()
{
    int blk = blockIdx.x;
    int l = blk & 1023;
    int x = (blk >> 10) & 3;
    int b = blk >> 12;
    int ny = x + 1;
    size_t pbase = ((size_t)(b*10 + c_tri[x]))*1048576 + (size_t)l*1024 + threadIdx.x*4;
    float4 v[4];
#pragma unroll
    for (int y = 0; y < 4; y++)
        if (y < ny) v[y] = *(const float4*)(g_s2 + pbase + (size_t)y*1048576);
        else        v[y] = make_float4(-1e30f,-1e30f,-1e30f,-1e30f);
    float4 mx;
    mx.x = fmaxf(fmaxf(v[0].x,v[1].x), fmaxf(v[2].x,v[3].x));
    mx.y = fmaxf(fmaxf(v[0].y,v[1].y), fmaxf(v[2].y,v[3].y));
    mx.z = fmaxf(fmaxf(v[0].z,v[1].z), fmaxf(v[2].z,v[3].z));
    mx.w = fmaxf(fmaxf(v[0].w,v[1].w), fmaxf(v[2].w,v[3].w));
    float4 s = make_float4(0,0,0,0);
#pragma unroll
    for (int y = 0; y < 4; y++) {
        if (y < ny) {
            v[y].x = expf(v[y].x - mx.x); s.x += v[y].x;
            v[y].y = expf(v[y].y - mx.y); s.y += v[y].y;
            v[y].z = expf(v[y].z - mx.z); s.z += v[y].z;
            v[y].w = expf(v[y].w - mx.w); s.w += v[y].w;
        }
    }
    float4 inv = make_float4(1.f/s.x, 1.f/s.y, 1.f/s.z, 1.f/s.w);
#pragma unroll
    for (int y = 0; y < 4; y++) {
        if (y < ny) {
            unsigned h0,l0,h1,l1;
            split_pack(v[y].x*inv.x, v[y].y*inv.y, h0, l0);
            split_pack(v[y].z*inv.z, v[y].w*inv.w, h1, l1);
            *(uint2*)(g_s2h + pbase + (size_t)y*1048576) = make_uint2(h0, h1);
            *(uint2*)(g_s2l + pbase + (size_t)y*1048576) = make_uint2(l0, l1);
        }
    }
}

// catt (NN, accumulate over y): V[b,l,e,x]
__global__ void __launch_bounds__(256) aa_t_catt()
{
    int bz = blockIdx.z, b = bz >> 2, x = bz & 3, ny = x + 1;
    float acc[2][4][4] = {};
    for (int y = 0; y < ny; y++) {
        size_t aoff = ((size_t)(b*10 + c_tri[x] + y))*1048576 + (size_t)blockIdx.y*128*1024;
        size_t boff = ((size_t)(bz*4 + y))*131072 + blockIdx.x*64;
        mma_core<1>(g_s2h + aoff, g_s2l + aoff, 1024, g_rh + boff, g_rl + boff, 128, 1024, acc);
    }
    const int lane = threadIdx.x & 31, w = threadIdx.x >> 5;
    const int g = lane >> 2, tg = lane & 3;
    const int wrow = w >> 1, wcol = w & 1;
    const int l0 = blockIdx.y*128, e0 = blockIdx.x*64;
#pragma unroll
    for (int mt = 0; mt < 2; mt++)
#pragma unroll
        for (int nt = 0; nt < 4; nt++) {
            int r = l0 + wrow*32 + mt*16 + g;
            int c = e0 + wcol*32 + nt*8 + 2*tg;
            g_vpart[(((size_t)b*1024 + r  )*128 + c  )*4 + x] = acc[mt][nt][0];
            g_vpart[(((size_t)b*1024 + r  )*128 + c+1)*4 + x] = acc[mt][nt][1];
            g_vpart[(((size_t)b*1024 + r+8)*128 + c  )*4 + x] = acc[mt][nt][2];
            g_vpart[(((size_t)b*1024 + r+8)*128 + c+1)*4 + x] = acc[mt][nt][3];
        }
}

// V output: g_vpart (viewed [8192,128]) @ Wv^T + bv — fp32, tiny
__global__ void __launch_bounds__(256) aa_k_vout(const float* __restrict__ Wv,
                                                 const float* __restrict__ bv,
                                                 float* __restrict__ out)
{
    gemm_nt_core(g_vpart, EE, Wv, EE, out, EE, EE, 1.0f, bv);
}

// series_out == 0.25 everywhere
__global__ void __launch_bounds__(256) aa_k_fill(float* __restrict__ p, float v)
{
    p[(size_t)blockIdx.x * 256 + threadIdx.x] = v;
}

// prior + sig (bit-exact libdevice path — DO NOT CHANGE)
__global__ void __launch_bounds__(256) aa_k_prior(const float* __restrict__ sigma,
                                                  float* __restrict__ prior,
                                                  float* __restrict__ sig_out)
{
    int row = blockIdx.x;
    int i = row & 1023;
    int h = (row >> 10) & 3;
    int b = row >> 12;
    float v = sigma[((size_t)b*LL + i)*XX + h];
    float s = sig_transform(v);
    if (threadIdx.x == 0) sig_out[row] = s;
    float denom = 2.5066282746310002f * s;
    float coef = 1.0f / denom;
    float s2 = s * s;
    float* p = prior + (size_t)row * LL;
    float fi = (float)i;
    for (int j = threadIdx.x; j < LL; j += 256) {
        float d = fabsf(fi - (float)j);
        float d2 = d * d;
        float num = -d2 * 0.5f;
        float arg = num / s2;
        p[j] = coef * expf(arg);
    }
}

// =========================================================================
extern "C" void kernel_launch(void* const* d_in, const int* in_sizes, int n_in,
                              void* d_out, int out_size)
{
    const float* big[5] = {};
    int nbig = 0;
    const float* sigma = nullptr;
    const float* w[2] = {};
    int nw = 0;
    const float* bias[2] = {};
    int nb = 0;
    for (int i = 0; i < n_in; i++) {
        int sz = in_sizes[i];
        if (sz == BB*LL*XX*EE)      { if (nbig < 5) big[nbig++] = (const float*)d_in[i]; }
        else if (sz == BB*LL*XX)    { sigma = (const float*)d_in[i]; }
        else if (sz == EE*EE)       { if (nw < 2) w[nw++] = (const float*)d_in[i]; }
        else if (sz == EE)          { if (nb < 2) bias[nb++] = (const float*)d_in[i]; }
    }
    const float* query = big[1];
    const float* key_  = big[2];
    const float* value = big[3];
    const float* qplus = big[4];
    const float* Wk = w[0];
    const float* Wv = w[1];    const float* bv = bias[1];

    float* out       = (float*)d_out;
    float* outV      = out;
    float* outSeries = out + 1048576;
    float* outPrior  = out + 1048576 + 8388608;
    float* outSig    = out + 1048576 + 2*8388608;

    dim3 thr(256);
    aa_cvt      <<<dim3(1024,5),   thr>>>(query, key_, value, qplus, Wk);
    aa_t_scores1<<<dim3(16,8,8),   thr>>>();
    aa_k_softmax<<<dim3(8192),     thr>>>();
    aa_t_retr   <<<dim3(8,8,8),    thr>>>();
    aa_t_qk     <<<dim3(2,64),     thr>>>();
    aa_t_scores2<<<dim3(16,8,20),  thr>>>();
    aa_k_softmax2<<<dim3(8192),    thr>>>();
    aa_t_catt   <<<dim3(2,8,8),    thr>>>();
    aa_k_vout   <<<dim3(2,128),    thr>>>(Wv, bv, outV);
    aa_k_fill   <<<dim3(8388608/256), thr>>>(outSeries, 0.25f);
    aa_k_prior  <<<dim3(8192),     thr>>>(sigma, outPrior, outSig);
}

// round 9
// speedup vs baseline: 2.0346x; 1.2848x over previous
#include <cuda_runtime.h>
#include <math.h>

#define BB 2
#define LL 1024
#define XX 4
#define EE 128
#define YY 4
#define SCALE 0.08838834764831845f   // 1/sqrt(128)

typedef unsigned short ushort_t;

// ---------------- scratch (static device globals) --------------------------
__device__ float g_search[8*1024*1024];                 // stage1 scores fp32  32 MB
__device__ float g_s2    [2*10*1024*1024];              // stage2 scores fp32  80 MB
__device__ float g_vpart [BB*LL*EE*XX];                 // [b][l][e][x]         4 MB

__device__ __align__(16) ushort_t g_qh [2*1024*4*128], g_ql [2*1024*4*128];
__device__ __align__(16) ushort_t g_kh [2*1024*4*128], g_kl [2*1024*4*128];
__device__ __align__(16) ushort_t g_vh [2*1024*512],   g_vl [2*1024*512];
__device__ __align__(16) ushort_t g_qph[2*1024*4*128], g_qpl[2*1024*4*128];
__device__ __align__(16) ushort_t g_wkh[128*128],      g_wkl[128*128];
__device__ __align__(16) ushort_t g_sh [8*1024*1024],  g_sl [8*1024*1024];   // Search bf16
__device__ __align__(16) ushort_t g_qkh[2*1024*4*128], g_qkl[2*1024*4*128];
__device__ __align__(16) ushort_t g_rh [2*4*4*1024*128], g_rl[2*4*4*1024*128];
__device__ __align__(16) ushort_t g_s2h[2*10*1024*1024], g_s2l[2*10*1024*1024];

__constant__ int c_xy_x[10] = {0,1,1,2,2,2,3,3,3,3};
__constant__ int c_xy_y[10] = {0,0,1,0,1,2,0,1,2,3};
__constant__ int c_tri[4]  = {0,1,3,6};

// libdevice path — bit-matches jax-on-GPU reference. DO NOT CHANGE.
__device__ __forceinline__ float sig_transform(float v) {
    float t = 5.0f * v;
    float e = expf(-t);
    float sigmoid = 1.0f / (1.0f + e);
    float sg = sigmoid + 1e-5f;
    float p = powf(3.0f, sg);
    return p - 1.0f;
}

// ================= bf16 split helpers =======================================
__device__ __forceinline__ unsigned bfbits(float x) {
    unsigned u = __float_as_uint(x);
    return (u + 0x7fffu + ((u >> 16) & 1u)) >> 16;
}
__device__ __forceinline__ float bfval(unsigned b) { return __uint_as_float(b << 16); }
__device__ __forceinline__ void split_pack(float x0, float x1, unsigned &hi, unsigned &lo) {
    unsigned h0 = bfbits(x0), h1 = bfbits(x1);
    unsigned l0 = bfbits(x0 - bfval(h0)), l1 = bfbits(x1 - bfval(h1));
    hi = h0 | (h1 << 16);
    lo = l0 | (l1 << 16);
}
__device__ __forceinline__ void mma_bf16(float (&c)[4],
    unsigned a0, unsigned a1, unsigned a2, unsigned a3,
    unsigned b0, unsigned b1)
{
    asm volatile("mma.sync.aligned.m16n8k16.row.col.f32.bf16.bf16.f32 "
        "{%0,%1,%2,%3},{%4,%5,%6,%7},{%8,%9},{%0,%1,%2,%3};"
        : "+f"(c[0]), "+f"(c[1]), "+f"(c[2]), "+f"(c[3])
        : "r"(a0), "r"(a1), "r"(a2), "r"(a3), "r"(b0), "r"(b1));
}
__device__ __forceinline__ void ldsm_x4(unsigned &r0, unsigned &r1,
                                        unsigned &r2, unsigned &r3, unsigned addr)
{
    asm volatile("ldmatrix.sync.aligned.m8n8.x4.shared.b16 {%0,%1,%2,%3}, [%4];"
        : "=r"(r0), "=r"(r1), "=r"(r2), "=r"(r3) : "r"(addr));
}
__device__ __forceinline__ void ldsm_x4t(unsigned &r0, unsigned &r1,
                                         unsigned &r2, unsigned &r3, unsigned addr)
{
    asm volatile("ldmatrix.sync.aligned.m8n8.x4.trans.shared.b16 {%0,%1,%2,%3}, [%4];"
        : "=r"(r0), "=r"(r1), "=r"(r2), "=r"(r3) : "r"(addr));
}

// C tile 128x64, 256 threads (8 warps = 4x2 grid of 32x32 warp tiles).
// Operands pre-split bf16 hi/lo in gmem; lda/ldb in bf16 elements.
// TRANSB=0: B is [n][k] (NT). TRANSB=1: B is [k][n] (NN, via ldmatrix.trans).
// Software-pipelined: gmem loads for chunk c+1 issued before computing chunk c.
template<int TRANSB>
__device__ __forceinline__ void mma_core(
    const ushort_t* __restrict__ Ahg, const ushort_t* __restrict__ Alg, int lda,
    const ushort_t* __restrict__ Bhg, const ushort_t* __restrict__ Blg, int ldb,
    int K, float (&acc)[2][4][4])
{
    __shared__ unsigned SA[5120];   // A: hi [0,2560) lo [2560,5120); 128 rows, pitch 20 words
    __shared__ unsigned SB[2560];   // B: hi [0,1280) lo [1280,2560); NT pitch 20, NN pitch 36
    const int tid = threadIdx.x;
    const int lane = tid & 31, w = tid >> 5;
    const int wrow = w >> 1, wcol = w & 1;
    const int lm = lane & 15, lq = lane >> 4;

    const int ar = tid >> 1, ax = tid & 1;    // A staging: 2 thr/row
    const int br = tid >> 2, bq = tid & 3;    // B NT: 4 thr/row
    const int half = tid >> 7, t7 = tid & 127;
    const int nr = t7 >> 2, nq = t7 & 3;      // B NN: 4 thr/k-row per half, 16 n each

    uint4 ra0, ra1, rl0, rl1;                 // A prefetch
    uint4 rb0, rm0;                           // B NT prefetch
    uint4 rn0, rn1;                           // B NN prefetch

    auto load_regs = [&](int kk) {
        const ushort_t* pa = Ahg + (size_t)ar*lda + kk + ax*16;
        const ushort_t* pl = Alg + (size_t)ar*lda + kk + ax*16;
        ra0 = *(const uint4*)pa; ra1 = *(const uint4*)(pa+8);
        rl0 = *(const uint4*)pl; rl1 = *(const uint4*)(pl+8);
        if (TRANSB) {
            const ushort_t* pb = (half ? Blg : Bhg) + (size_t)(kk + nr)*ldb + nq*16;
            rn0 = *(const uint4*)pb;
            rn1 = *(const uint4*)(pb+8);
        } else {
            const ushort_t* pb = Bhg + (size_t)br*ldb + kk + bq*8;
            const ushort_t* pm = Blg + (size_t)br*ldb + kk + bq*8;
            rb0 = *(const uint4*)pb;
            rm0 = *(const uint4*)pm;
        }
    };
    auto store_smem = [&]() {
        *(uint4*)&SA[ar*20 + ax*8]            = ra0;
        *(uint4*)&SA[ar*20 + ax*8 + 4]        = ra1;
        *(uint4*)&SA[2560 + ar*20 + ax*8]     = rl0;
        *(uint4*)&SA[2560 + ar*20 + ax*8 + 4] = rl1;
        if (TRANSB) {
            ushort_t* bd = (ushort_t*)(SB + half*1280) + nr*72 + nq*16;
            *(uint4*)bd     = rn0;
            *(uint4*)(bd+8) = rn1;
        } else {
            *(uint4*)&SB[br*20 + bq*4]        = rb0;
            *(uint4*)&SB[1280 + br*20 + bq*4] = rm0;
        }
    };

    const int nck = K >> 5;
    load_regs(0);
    for (int c = 0; c < nck; c++) {
        __syncthreads();                // smem free (prev chunk consumed)
        store_smem();
        if (c + 1 < nck) load_regs((c+1) << 5);
        __syncthreads();
#pragma unroll
        for (int k16 = 0; k16 < 2; k16++) {
            const int ko = k16*8;
            unsigned ah[2][4], al[2][4], bh[4][2], bl[4][2];
#pragma unroll
            for (int mt = 0; mt < 2; mt++) {
                int m = wrow*32 + mt*16;
                unsigned aw = (unsigned)__cvta_generic_to_shared(
                    &SA[(m + lm)*20 + ko + (lq<<2)]);
                ldsm_x4(ah[mt][0], ah[mt][1], ah[mt][2], ah[mt][3], aw);
                ldsm_x4(al[mt][0], al[mt][1], al[mt][2], al[mt][3], aw + 2560*4);
            }
#pragma unroll
            for (int p = 0; p < 2; p++) {
                int n0 = wcol*32 + p*16;
                if (TRANSB) {
                    const ushort_t* bb = (const ushort_t*)SB;
                    unsigned bw = (unsigned)__cvta_generic_to_shared(
                        bb + (k16*16 + lm)*72 + n0 + (lq<<3));
                    ldsm_x4t(bh[2*p][0], bh[2*p][1], bh[2*p+1][0], bh[2*p+1][1], bw);
                    ldsm_x4t(bl[2*p][0], bl[2*p][1], bl[2*p+1][0], bl[2*p+1][1], bw + 1280*4);
                } else {
                    unsigned bw = (unsigned)__cvta_generic_to_shared(
                        &SB[(n0 + lm)*20 + ko + (lq<<2)]);
                    ldsm_x4(bh[2*p][0], bh[2*p+1][0], bh[2*p][1], bh[2*p+1][1], bw);
                    ldsm_x4(bl[2*p][0], bl[2*p+1][0], bl[2*p][1], bl[2*p+1][1], bw + 1280*4);
                }
            }
#pragma unroll
            for (int mt = 0; mt < 2; mt++)
#pragma unroll
                for (int nt = 0; nt < 4; nt++) {
                    mma_bf16(acc[mt][nt], ah[mt][0],ah[mt][1],ah[mt][2],ah[mt][3], bh[nt][0],bh[nt][1]);
                    mma_bf16(acc[mt][nt], ah[mt][0],ah[mt][1],ah[mt][2],ah[mt][3], bl[nt][0],bl[nt][1]);
                    mma_bf16(acc[mt][nt], al[mt][0],al[mt][1],al[mt][2],al[mt][3], bh[nt][0],bh[nt][1]);
                }
        }
    }
}

__device__ __forceinline__ void epilogue_f32(
    float (&acc)[2][4][4], float* C, int ldc, float scale)
{
    const int lane = threadIdx.x & 31, w = threadIdx.x >> 5;
    const int g = lane >> 2, tg = lane & 3;
    const int wrow = w >> 1, wcol = w & 1;
#pragma unroll
    for (int mt = 0; mt < 2; mt++)
#pragma unroll
        for (int nt = 0; nt < 4; nt++) {
            int r0 = wrow*32 + mt*16 + g;
            int c0 = wcol*32 + nt*8 + 2*tg;
            float2 v0 = {acc[mt][nt][0]*scale, acc[mt][nt][1]*scale};
            float2 v1 = {acc[mt][nt][2]*scale, acc[mt][nt][3]*scale};
            *(float2*)(C + (size_t)r0*ldc + c0) = v0;
            *(float2*)(C + (size_t)(r0+8)*ldc + c0) = v1;
        }
}

__device__ __forceinline__ void epilogue_bf16(
    float (&acc)[2][4][4], ushort_t* Ch, ushort_t* Cl, int ldc)
{
    const int lane = threadIdx.x & 31, w = threadIdx.x >> 5;
    const int g = lane >> 2, tg = lane & 3;
    const int wrow = w >> 1, wcol = w & 1;
#pragma unroll
    for (int mt = 0; mt < 2; mt++)
#pragma unroll
        for (int nt = 0; nt < 4; nt++) {
            int r0 = wrow*32 + mt*16 + g;
            int c0 = wcol*32 + nt*8 + 2*tg;
            unsigned h, l;
            split_pack(acc[mt][nt][0], acc[mt][nt][1], h, l);
            *(unsigned*)(Ch + (size_t)r0*ldc + c0) = h;
            *(unsigned*)(Cl + (size_t)r0*ldc + c0) = l;
            split_pack(acc[mt][nt][2], acc[mt][nt][3], h, l);
            *(unsigned*)(Ch + (size_t)(r0+8)*ldc + c0) = h;
            *(unsigned*)(Cl + (size_t)(r0+8)*ldc + c0) = l;
        }
}

// ---------------- fp32 NT core (vout only) ---------------------------------
__device__ __forceinline__ void gemm_nt_core(
    const float* __restrict__ A, int lda,
    const float* __restrict__ B, int ldb,
    float* __restrict__ C, int ldc,
    int K, float scale, const float* __restrict__ bias)
{
    __shared__ float As[16*68];
    __shared__ float Bs[16*68];
    const int tid = threadIdx.x;
    const int tx = tid & 15, ty = tid >> 4;
    const int lr = tid >> 2;
    const int lk = (tid & 3) << 2;
    const int row0 = blockIdx.y * 64;
    const int col0 = blockIdx.x * 64;
    const float* Ap = A + (size_t)(row0 + lr) * lda + lk;
    const float* Bp = B + (size_t)(col0 + lr) * ldb + lk;
    float acc[4][4] = {};
    for (int kk = 0; kk < K; kk += 16) {
        float4 av = *(const float4*)(Ap + kk);
        float4 bv = *(const float4*)(Bp + kk);
        __syncthreads();
        As[(lk+0)*68+lr]=av.x; As[(lk+1)*68+lr]=av.y;
        As[(lk+2)*68+lr]=av.z; As[(lk+3)*68+lr]=av.w;
        Bs[(lk+0)*68+lr]=bv.x; Bs[(lk+1)*68+lr]=bv.y;
        Bs[(lk+2)*68+lr]=bv.z; Bs[(lk+3)*68+lr]=bv.w;
        __syncthreads();
#pragma unroll
        for (int k = 0; k < 16; k++) {
            float4 a4 = *(const float4*)&As[k*68 + ty*4];
            float4 b4 = *(const float4*)&Bs[k*68 + tx*4];
            float a_[4] = {a4.x, a4.y, a4.z, a4.w};
            float b_[4] = {b4.x, b4.y, b4.z, b4.w};
#pragma unroll
            for (int i = 0; i < 4; i++)
#pragma unroll
                for (int j = 0; j < 4; j++)
                    acc[i][j] = fmaf(a_[i], b_[j], acc[i][j]);
        }
    }
#pragma unroll
    for (int i = 0; i < 4; i++) {
        float4 o;
        o.x = acc[i][0]*scale + bias[col0+tx*4+0];
        o.y = acc[i][1]*scale + bias[col0+tx*4+1];
        o.z = acc[i][2]*scale + bias[col0+tx*4+2];
        o.w = acc[i][3]*scale + bias[col0+tx*4+3];
        *(float4*)&C[(size_t)(row0+ty*4+i)*ldc + col0 + tx*4] = o;
    }
}

// ================= kernels ==================================================

// split fp32 inputs -> bf16 hi/lo
__global__ void __launch_bounds__(256) aa_cvt(
    const float* __restrict__ q, const float* __restrict__ k,
    const float* __restrict__ val, const float* __restrict__ qp,
    const float* __restrict__ Wk)
{
    const float* src; ushort_t *dh, *dl; int n;
    switch (blockIdx.y) {
        case 0: src = q;   dh = g_qh;  dl = g_ql;  n = 1048576; break;
        case 1: src = k;   dh = g_kh;  dl = g_kl;  n = 1048576; break;
        case 2: src = val; dh = g_vh;  dl = g_vl;  n = 1048576; break;
        case 3: src = qp;  dh = g_qph; dl = g_qpl; n = 1048576; break;
        default:src = Wk;  dh = g_wkh; dl = g_wkl; n = 16384;   break;
    }
    int i = (blockIdx.x * 256 + threadIdx.x) * 4;
    if (i >= n) return;
    float4 v = *(const float4*)(src + i);
    unsigned h0,l0,h1,l1;
    split_pack(v.x, v.y, h0, l0);
    split_pack(v.z, v.w, h1, l1);
    *(uint2*)(dh + i) = make_uint2(h0, h1);
    *(uint2*)(dl + i) = make_uint2(l0, l1);
}

// stage 1 scores: g_search = scale * Q K^T
__global__ void __launch_bounds__(256) aa_t_scores1()
{
    int bz = blockIdx.z, b = bz >> 2, x = bz & 3;
    size_t qoff = (size_t)b*524288 + x*128;
    const ushort_t* Ah = g_qh + qoff + (size_t)blockIdx.y*128*512;
    const ushort_t* Al = g_ql + qoff + (size_t)blockIdx.y*128*512;
    const ushort_t* Bh = g_kh + qoff + (size_t)blockIdx.x*64*512;
    const ushort_t* Bl = g_kl + qoff + (size_t)blockIdx.x*64*512;
    float acc[2][4][4] = {};
    mma_core<0>(Ah, Al, 512, Bh, Bl, 512, 128, acc);
    float* C = g_search + (size_t)bz*1048576 + (size_t)blockIdx.y*128*1024 + blockIdx.x*64;
    epilogue_f32(acc, C, 1024, SCALE);
}

// row softmax over s; emits bf16 hi/lo Search
__global__ void __launch_bounds__(256) aa_k_softmax()
{
    size_t row = blockIdx.x;
    const float* p = g_search + row * 1024;
    int tid = threadIdx.x;
    float4 v4 = *(const float4*)(p + tid*4);
    float v[4] = {v4.x, v4.y, v4.z, v4.w};
    float m = fmaxf(fmaxf(v[0], v[1]), fmaxf(v[2], v[3]));
    __shared__ float red[256];
    red[tid] = m; __syncthreads();
    for (int s = 128; s > 0; s >>= 1) {
        if (tid < s) red[tid] = fmaxf(red[tid], red[tid+s]);
        __syncthreads();
    }
    m = red[0]; __syncthreads();
    float sum = 0.f;
#pragma unroll
    for (int i = 0; i < 4; i++) { v[i] = expf(v[i] - m); sum += v[i]; }
    red[tid] = sum; __syncthreads();
    for (int s = 128; s > 0; s >>= 1) {
        if (tid < s) red[tid] += red[tid+s];
        __syncthreads();
    }
    float inv = 1.f / red[0];
    unsigned h0,l0,h1,l1;
    split_pack(v[0]*inv, v[1]*inv, h0, l0);
    split_pack(v[2]*inv, v[3]*inv, h1, l1);
    *(uint2*)(g_sh + row*1024 + tid*4) = make_uint2(h0, h1);
    *(uint2*)(g_sl + row*1024 + tid*4) = make_uint2(l0, l1);
}

// Retrieval planes (NN): out bf16 hi/lo g_r[plane][m][e]
__global__ void __launch_bounds__(256) aa_t_retr()
{
    int bz = blockIdx.z, b = bz >> 2, x = bz & 3;
    int n0 = blockIdx.x * 64;
    if (n0 >= (x + 1) * 128) return;
    const ushort_t* Ah = g_sh + (size_t)bz*1048576 + (size_t)blockIdx.y*128*1024;
    const ushort_t* Al = g_sl + (size_t)bz*1048576 + (size_t)blockIdx.y*128*1024;
    const ushort_t* Bh = g_vh + (size_t)b*524288 + n0;
    const ushort_t* Bl = g_vl + (size_t)b*524288 + n0;
    float acc[2][4][4] = {};
    mma_core<1>(Ah, Al, 1024, Bh, Bl, 512, 1024, acc);
    int y = n0 >> 7;
    size_t coff = ((size_t)(bz*4 + y))*131072 + (size_t)blockIdx.y*128*128 + (n0 & 127);
    epilogue_bf16(acc, g_rh + coff, g_rl + coff, 128);
}

// qk = q_plus @ Wk (NN, bias cancels in softmax) -> bf16 hi/lo
__global__ void __launch_bounds__(256) aa_t_qk()
{
    const ushort_t* Ah = g_qph + (size_t)blockIdx.y*128*128;
    const ushort_t* Al = g_qpl + (size_t)blockIdx.y*128*128;
    float acc[2][4][4] = {};
    mma_core<1>(Ah, Al, 128, g_wkh + blockIdx.x*64, g_wkl + blockIdx.x*64, 128, 128, acc);
    size_t coff = (size_t)blockIdx.y*128*128 + blockIdx.x*64;
    epilogue_bf16(acc, g_qkh + coff, g_qkl + coff, 128);
}

// stage-2 scores planes (NT): g_s2[plane] = scale * qk · R^T
__global__ void __launch_bounds__(256) aa_t_scores2()
{
    int t = blockIdx.z, b = t / 10, u = t % 10;
    int x = c_xy_x[u], y = c_xy_y[u];
    size_t aoff = (size_t)b*524288 + x*128 + (size_t)blockIdx.y*128*512;
    size_t boff = ((size_t)((b*4 + x)*4 + y))*131072 + (size_t)blockIdx.x*64*128;
    float acc[2][4][4] = {};
    mma_core<0>(g_qkh + aoff, g_qkl + aoff, 512, g_rh + boff, g_rl + boff, 128, 128, acc);
    float* C = g_s2 + ((size_t)(b*10 + u))*1048576
             + (size_t)blockIdx.y*128*1024 + blockIdx.x*64;
    epilogue_f32(acc, C, 1024, SCALE);
}

// softmax over y across planes -> series bf16 hi/lo
__global__ void __launch_bounds__(256) aa_k_softmax2()
{
    int blk = blockIdx.x;
    int l = blk & 1023;
    int x = (blk >> 10) & 3;
    int b = blk >> 12;
    int ny = x + 1;
    size_t pbase = ((size_t)(b*10 + c_tri[x]))*1048576 + (size_t)l*1024 + threadIdx.x*4;
    float4 v[4];
#pragma unroll
    for (int y = 0; y < 4; y++)
        if (y < ny) v[y] = *(const float4*)(g_s2 + pbase + (size_t)y*1048576);
        else        v[y] = make_float4(-1e30f,-1e30f,-1e30f,-1e30f);
    float4 mx;
    mx.x = fmaxf(fmaxf(v[0].x,v[1].x), fmaxf(v[2].x,v[3].x));
    mx.y = fmaxf(fmaxf(v[0].y,v[1].y), fmaxf(v[2].y,v[3].y));
    mx.z = fmaxf(fmaxf(v[0].z,v[1].z), fmaxf(v[2].z,v[3].z));
    mx.w = fmaxf(fmaxf(v[0].w,v[1].w), fmaxf(v[2].w,v[3].w));
    float4 s = make_float4(0,0,0,0);
#pragma unroll
    for (int y = 0; y < 4; y++) {
        if (y < ny) {
            v[y].x = expf(v[y].x - mx.x); s.x += v[y].x;
            v[y].y = expf(v[y].y - mx.y); s.y += v[y].y;
            v[y].z = expf(v[y].z - mx.z); s.z += v[y].z;
            v[y].w = expf(v[y].w - mx.w); s.w += v[y].w;
        }
    }
    float4 inv = make_float4(1.f/s.x, 1.f/s.y, 1.f/s.z, 1.f/s.w);
#pragma unroll
    for (int y = 0; y < 4; y++) {
        if (y < ny) {
            unsigned h0,l0,h1,l1;
            split_pack(v[y].x*inv.x, v[y].y*inv.y, h0, l0);
            split_pack(v[y].z*inv.z, v[y].w*inv.w, h1, l1);
            *(uint2*)(g_s2h + pbase + (size_t)y*1048576) = make_uint2(h0, h1);
            *(uint2*)(g_s2l + pbase + (size_t)y*1048576) = make_uint2(l0, l1);
        }
    }
}

// catt (NN, accumulate over y): V[b,l,e,x]
__global__ void __launch_bounds__(256) aa_t_catt()
{
    int bz = blockIdx.z, b = bz >> 2, x = bz & 3, ny = x + 1;
    float acc[2][4][4] = {};
    for (int y = 0; y < ny; y++) {
        size_t aoff = ((size_t)(b*10 + c_tri[x] + y))*1048576 + (size_t)blockIdx.y*128*1024;
        size_t boff = ((size_t)(bz*4 + y))*131072 + blockIdx.x*64;
        mma_core<1>(g_s2h + aoff, g_s2l + aoff, 1024, g_rh + boff, g_rl + boff, 128, 1024, acc);
    }
    const int lane = threadIdx.x & 31, w = threadIdx.x >> 5;
    const int g = lane >> 2, tg = lane & 3;
    const int wrow = w >> 1, wcol = w & 1;
    const int l0 = blockIdx.y*128, e0 = blockIdx.x*64;
#pragma unroll
    for (int mt = 0; mt < 2; mt++)
#pragma unroll
        for (int nt = 0; nt < 4; nt++) {
            int r = l0 + wrow*32 + mt*16 + g;
            int c = e0 + wcol*32 + nt*8 + 2*tg;
            g_vpart[(((size_t)b*1024 + r  )*128 + c  )*4 + x] = acc[mt][nt][0];
            g_vpart[(((size_t)b*1024 + r  )*128 + c+1)*4 + x] = acc[mt][nt][1];
            g_vpart[(((size_t)b*1024 + r+8)*128 + c  )*4 + x] = acc[mt][nt][2];
            g_vpart[(((size_t)b*1024 + r+8)*128 + c+1)*4 + x] = acc[mt][nt][3];
        }
}

// V output: g_vpart (viewed [8192,128]) @ Wv^T + bv — fp32, tiny
__global__ void __launch_bounds__(256) aa_k_vout(const float* __restrict__ Wv,
                                                 const float* __restrict__ bv,
                                                 float* __restrict__ out)
{
    gemm_nt_core(g_vpart, EE, Wv, EE, out, EE, EE, 1.0f, bv);
}

// series_out == 0.25 everywhere (float4)
__global__ void __launch_bounds__(256) aa_k_fill(float4* __restrict__ p, float v)
{
    p[(size_t)blockIdx.x * 256 + threadIdx.x] = make_float4(v, v, v, v);
}

// prior + sig (bit-exact libdevice path — DO NOT CHANGE)
__global__ void __launch_bounds__(256) aa_k_prior(const float* __restrict__ sigma,
                                                  float* __restrict__ prior,
                                                  float* __restrict__ sig_out)
{
    int row = blockIdx.x;
    int i = row & 1023;
    int h = (row >> 10) & 3;
    int b = row >> 12;
    float v = sigma[((size_t)b*LL + i)*XX + h];
    float s = sig_transform(v);
    if (threadIdx.x == 0) sig_out[row] = s;
    float denom = 2.5066282746310002f * s;
    float coef = 1.0f / denom;
    float s2 = s * s;
    float* p = prior + (size_t)row * LL;
    float fi = (float)i;
    for (int j = threadIdx.x; j < LL; j += 256) {
        float d = fabsf(fi - (float)j);
        float d2 = d * d;
        float num = -d2 * 0.5f;
        float arg = num / s2;
        p[j] = coef * expf(arg);
    }
}

// =========================================================================
extern "C" void kernel_launch(void* const* d_in, const int* in_sizes, int n_in,
                              void* d_out, int out_size)
{
    const float* big[5] = {};
    int nbig = 0;
    const float* sigma = nullptr;
    const float* w[2] = {};
    int nw = 0;
    const float* bias[2] = {};
    int nb = 0;
    for (int i = 0; i < n_in; i++) {
        int sz = in_sizes[i];
        if (sz == BB*LL*XX*EE)      { if (nbig < 5) big[nbig++] = (const float*)d_in[i]; }
        else if (sz == BB*LL*XX)    { sigma = (const float*)d_in[i]; }
        else if (sz == EE*EE)       { if (nw < 2) w[nw++] = (const float*)d_in[i]; }
        else if (sz == EE)          { if (nb < 2) bias[nb++] = (const float*)d_in[i]; }
    }
    const float* query = big[1];
    const float* key_  = big[2];
    const float* value = big[3];
    const float* qplus = big[4];
    const float* Wk = w[0];
    const float* Wv = w[1];    const float* bv = bias[1];

    float* out       = (float*)d_out;
    float* outV      = out;
    float* outSeries = out + 1048576;
    float* outPrior  = out + 1048576 + 8388608;
    float* outSig    = out + 1048576 + 2*8388608;

    dim3 thr(256);
    aa_cvt      <<<dim3(1024,5),   thr>>>(query, key_, value, qplus, Wk);
    aa_t_scores1<<<dim3(16,8,8),   thr>>>();
    aa_k_softmax<<<dim3(8192),     thr>>>();
    aa_t_retr   <<<dim3(8,8,8),    thr>>>();
    aa_t_qk     <<<dim3(2,64),     thr>>>();
    aa_t_scores2<<<dim3(16,8,20),  thr>>>();
    aa_k_softmax2<<<dim3(8192),    thr>>>();
    aa_t_catt   <<<dim3(2,8,8),    thr>>>();
    aa_k_vout   <<<dim3(2,128),    thr>>>(Wv, bv, outV);
    aa_k_fill   <<<dim3(8192),     thr>>>((float4*)outSeries, 0.25f);
    aa_k_prior  <<<dim3(8192),     thr>>>(sigma, outPrior, outSig);
}